// round 3
// baseline (speedup 1.0000x reference)
#include <cuda_runtime.h>
#include <cuda_bf16.h>
#include <math.h>

#define B_  4
#define S_  2048
#define D_  2048
#define H_  16
#define HD_ 128
#define RD_ 64
#define QL_ 512
#define KL_ 512
#define MT  (B_*S_)
#define DK_ 576
#define SM_SCALE 0.07216878364870323f  // 1/sqrt(192)

// ------------------- scratch (device globals; no runtime allocs) ------------
__device__ float g_qc   [(size_t)MT * QL_];
__device__ float g_qnope[(size_t)MT * D_];
__device__ float g_qrope[(size_t)MT * (H_ * RD_)];
__device__ float g_kv   [(size_t)MT * KL_];
__device__ float g_krope[(size_t)MT * RD_];
__device__ float g_qabs [(size_t)H_ * MT * KL_];
__device__ float g_lat  [(size_t)H_ * MT * KL_];
__device__ float g_outhd[(size_t)MT * D_];

// ------------------- generic SGEMM -------------------------------------------
// C[M,N] = A @ B(^T) (+bias) (*sigmoid(gates[z])), 128x128 tile, BK=8.
// TRANSB: B is [N,K] row-major; else B is [K,N] row-major. Batched over z.
template<bool TRANSB>
__global__ __launch_bounds__(256) void gemm_kernel(
    const float* __restrict__ A, int lda, long long sAz,
    const float* __restrict__ B, int ldb, long long sBz,
    float* __restrict__ C, int ldc, long long sCz,
    int N, int K,
    const float* __restrict__ bias,
    const float* __restrict__ gates)
{
    __shared__ float sA[8][128];
    __shared__ float sB[8][128];
    const int z = blockIdx.z;
    A += (long long)z * sAz;  B += (long long)z * sBz;  C += (long long)z * sCz;

    const int tid = threadIdx.x;
    const int m0 = blockIdx.y * 128, n0 = blockIdx.x * 128;
    const int ty = tid >> 4, tx = tid & 15;
    const int am = tid >> 1;                // 0..127
    const int ak = (tid & 1) * 4;           // 0 or 4

    float acc[8][8];
#pragma unroll
    for (int i = 0; i < 8; i++)
#pragma unroll
        for (int j = 0; j < 8; j++) acc[i][j] = 0.f;

    for (int k0 = 0; k0 < K; k0 += 8) {
        float4 av = *(const float4*)(A + (long long)(m0 + am) * lda + (k0 + ak));
        if (TRANSB) {
            float4 bv = make_float4(0.f, 0.f, 0.f, 0.f);
            if (n0 + am < N)
                bv = *(const float4*)(B + (long long)(n0 + am) * ldb + (k0 + ak));
            sB[ak + 0][am] = bv.x; sB[ak + 1][am] = bv.y;
            sB[ak + 2][am] = bv.z; sB[ak + 3][am] = bv.w;
        } else {
            const int kb = (tid * 4) >> 7;      // 0..7
            const int nb = (tid * 4) & 127;
            float4 bv = make_float4(0.f, 0.f, 0.f, 0.f);
            if (n0 + nb < N)
                bv = *(const float4*)(B + (long long)(k0 + kb) * ldb + (n0 + nb));
            *(float4*)&sB[kb][nb] = bv;
        }
        sA[ak + 0][am] = av.x; sA[ak + 1][am] = av.y;
        sA[ak + 2][am] = av.z; sA[ak + 3][am] = av.w;
        __syncthreads();

#pragma unroll
        for (int kk = 0; kk < 8; kk++) {
            float a[8], b[8];
            *(float4*)(a)     = *(const float4*)&sA[kk][ty * 4];
            *(float4*)(a + 4) = *(const float4*)&sA[kk][64 + ty * 4];
            *(float4*)(b)     = *(const float4*)&sB[kk][tx * 4];
            *(float4*)(b + 4) = *(const float4*)&sB[kk][64 + tx * 4];
#pragma unroll
            for (int i = 0; i < 8; i++)
#pragma unroll
                for (int j = 0; j < 8; j++) acc[i][j] += a[i] * b[j];
        }
        __syncthreads();
    }

    float scale = 1.f;
    if (gates) scale = 1.f / (1.f + expf(-gates[z]));
#pragma unroll
    for (int i = 0; i < 8; i++) {
        const int m = m0 + ((i < 4) ? (ty * 4 + i) : (60 + ty * 4 + i));
#pragma unroll
        for (int j = 0; j < 8; j++) {
            const int n = n0 + ((j < 4) ? (tx * 4 + j) : (60 + tx * 4 + j));
            if (n < N) {
                float v = acc[i][j];
                if (bias) v += bias[n];
                C[(long long)m * ldc + n] = v * scale;
            }
        }
    }
}

// ------------------- rmsnorm (in place), one block (128 thr) per row ---------
__global__ void rmsnorm_kernel(float* __restrict__ data,
                               const float* __restrict__ gamma, int width)
{
    float* p = data + (long long)blockIdx.x * width;
    const int tid = threadIdx.x;
    float ss = 0.f;
    for (int i = tid * 4; i < width; i += 512) {
        float4 v = *(const float4*)(p + i);
        ss += v.x * v.x + v.y * v.y + v.z * v.z + v.w * v.w;
    }
#pragma unroll
    for (int off = 16; off; off >>= 1) ss += __shfl_xor_sync(~0u, ss, off);
    __shared__ float ws[4];
    if ((tid & 31) == 0) ws[tid >> 5] = ss;
    __syncthreads();
    const float inv = rsqrtf((ws[0] + ws[1] + ws[2] + ws[3]) / (float)width + 1e-6f);
    for (int i = tid * 4; i < width; i += 512) {
        float4 v = *(const float4*)(p + i);
        float4 g = *(const float4*)(gamma + i);
        v.x *= inv * g.x; v.y *= inv * g.y; v.z *= inv * g.z; v.w *= inv * g.w;
        *(float4*)(p + i) = v;
    }
}

// ------------------- RoPE (in place) -----------------------------------------
__device__ __forceinline__ void rope_pair(float* p, int i, int m)
{
    const float x1 = p[i], x2 = p[i + 32];
    const float pos = (float)(m & (S_ - 1));
    const float inv_freq = exp2f(-(float)i * (13.287712379549449f / 32.f));
    float sn, cs;
    sincosf(pos * inv_freq, &sn, &cs);
    p[i]      = x1 * cs - x2 * sn;
    p[i + 32] = x1 * sn + x2 * cs;
}

__global__ void rope_q_kernel(float* __restrict__ q)  // [MT][H*64]
{
    const int idx = blockIdx.x * 256 + threadIdx.x;
    const int i = idx & 31, rest = idx >> 5;
    const int h = rest & (H_ - 1), m = rest >> 4;
    rope_pair(q + (long long)m * (H_ * RD_) + h * RD_, i, m);
}

__global__ void rope_k_kernel(float* __restrict__ k)  // [MT][64]
{
    const int idx = blockIdx.x * 256 + threadIdx.x;
    const int i = idx & 31, m = idx >> 5;
    rope_pair(k + (long long)m * RD_, i, m);
}

// ------------------- fused causal flash attention over the latent ------------
// grid (qtile=64, h=16, b=4), 256 threads, BM=BN=32.
__global__ __launch_bounds__(256, 1) void mla_attn_kernel(
    const float* __restrict__ qabs,   // [H][MT][512]
    const float* __restrict__ qrope,  // [MT][H*64]
    const float* __restrict__ kv,     // [MT][512]
    const float* __restrict__ krope,  // [MT][64]
    float* __restrict__ lat)          // [H][MT][512]
{
    extern __shared__ float sm[];
    float* sQ     = sm;               // [576][33] k-major, +1 skew
    float* sK     = sQ + DK_ * 33;    // [576][33]
    float* sP     = sK + DK_ * 33;    // [32][33]
    float* sAlpha = sP + 32 * 33;     // 32
    float* sL     = sAlpha + 32;      // 32

    const int qt = blockIdx.x, h = blockIdx.y, b = blockIdx.z;
    const int tid = threadIdx.x, lane = tid & 31;
    const long long mbase = (long long)b * S_;
    const int q0 = qt * 32;

    {   // Q tile transposed into smem: sQ[k][r] = [qabs | qrope]
        const float* qa = qabs + ((long long)h * MT + mbase + q0) * KL_;
        const float* qr = qrope + (mbase + q0) * (H_ * RD_) + h * RD_;
        for (int lin = tid; lin < 32 * DK_; lin += 256) {
            const int r = lin / DK_, k = lin - r * DK_;
            sQ[k * 33 + r] = (k < KL_) ? qa[(long long)r * KL_ + k]
                                       : qr[(long long)r * (H_ * RD_) + (k - KL_)];
        }
    }

    const int g  = tid >> 4;            // score row pair 0..15
    const int jb = (tid & 15) * 2;      // score col pair base
    float mi0 = -INFINITY, mi1 = -INFINITY, li0 = 0.f, li1 = 0.f;

    const int pr = (tid >> 6) * 8;      // PV rows
    const int pc = (tid & 63) * 8;      // PV latent cols
    float acc[8][8];
#pragma unroll
    for (int i = 0; i < 8; i++)
#pragma unroll
        for (int j = 0; j < 8; j++) acc[i][j] = 0.f;

    for (int tt = 0; tt <= qt; tt++) {
        const int t0 = tt * 32;
        __syncthreads();                // sK/sP readers of prev iter done
        {
            const float* kvp = kv + (mbase + t0) * KL_;
            const float* krp = krope + (mbase + t0) * RD_;
            for (int lin = tid; lin < 32 * DK_; lin += 256) {
                const int r = lin / DK_, k = lin - r * DK_;
                sK[k * 33 + r] = (k < KL_) ? kvp[(long long)r * KL_ + k]
                                           : krp[(long long)r * RD_ + (k - KL_)];
            }
        }
        __syncthreads();

        // scores: 2x2 per thread over k=576
        float s00 = 0.f, s01 = 0.f, s10 = 0.f, s11 = 0.f;
        {
            const float* qp = sQ + 2 * g;
            const float* kp = sK + jb;
#pragma unroll 4
            for (int k = 0; k < DK_; k++) {
                const float a0 = qp[0], a1 = qp[1];
                const float b0 = kp[0], b1 = kp[1];
                s00 += a0 * b0; s01 += a0 * b1;
                s10 += a1 * b0; s11 += a1 * b1;
                qp += 33; kp += 33;
            }
        }
        const int r0 = q0 + 2 * g, r1 = r0 + 1;
        const int c0 = t0 + jb,    c1 = c0 + 1;
        s00 = (c0 <= r0) ? s00 * SM_SCALE : -INFINITY;
        s01 = (c1 <= r0) ? s01 * SM_SCALE : -INFINITY;
        s10 = (c0 <= r1) ? s10 * SM_SCALE : -INFINITY;
        s11 = (c1 <= r1) ? s11 * SM_SCALE : -INFINITY;

        float mx0 = fmaxf(s00, s01), mx1 = fmaxf(s10, s11);
#pragma unroll
        for (int off = 1; off < 16; off <<= 1) {
            mx0 = fmaxf(mx0, __shfl_xor_sync(~0u, mx0, off, 16));
            mx1 = fmaxf(mx1, __shfl_xor_sync(~0u, mx1, off, 16));
        }
        const float mn0 = fmaxf(mi0, mx0), mn1 = fmaxf(mi1, mx1);
        const float p00 = expf(s00 - mn0), p01 = expf(s01 - mn0);
        const float p10 = expf(s10 - mn1), p11 = expf(s11 - mn1);
        float rs0 = p00 + p01, rs1 = p10 + p11;
#pragma unroll
        for (int off = 1; off < 16; off <<= 1) {
            rs0 += __shfl_xor_sync(~0u, rs0, off, 16);
            rs1 += __shfl_xor_sync(~0u, rs1, off, 16);
        }
        const float a0 = expf(mi0 - mn0), a1 = expf(mi1 - mn1);
        li0 = li0 * a0 + rs0;  li1 = li1 * a1 + rs1;
        mi0 = mn0;  mi1 = mn1;

        sP[(2 * g) * 33 + jb]         = p00;
        sP[(2 * g) * 33 + jb + 1]     = p01;
        sP[(2 * g + 1) * 33 + jb]     = p10;
        sP[(2 * g + 1) * 33 + jb + 1] = p11;
        if ((tid & 15) == 0) { sAlpha[2 * g] = a0; sAlpha[2 * g + 1] = a1; }
        __syncthreads();

        // acc = acc*alpha + P @ kv_tile
        float al[8];
#pragma unroll
        for (int i = 0; i < 8; i++) al[i] = sAlpha[pr + i];
#pragma unroll
        for (int i = 0; i < 8; i++)
#pragma unroll
            for (int j = 0; j < 8; j++) acc[i][j] *= al[i];

#pragma unroll 4
        for (int jj = 0; jj < 32; jj++) {
            const int j = (jj + lane) & 31;     // lane rotation: conflict-free
            float pv[8], bv[8];
#pragma unroll
            for (int i = 0; i < 8; i++) pv[i] = sP[(pr + i) * 33 + j];
#pragma unroll
            for (int i = 0; i < 8; i++) bv[i] = sK[(pc + i) * 33 + j];
#pragma unroll
            for (int i = 0; i < 8; i++)
#pragma unroll
                for (int j2 = 0; j2 < 8; j2++) acc[i][j2] += pv[i] * bv[j2];
        }
    }

    if ((tid & 15) == 0) { sL[2 * g] = li0; sL[2 * g + 1] = li1; }
    __syncthreads();

    float* outp = lat + ((long long)h * MT + mbase + q0) * KL_;
#pragma unroll
    for (int i = 0; i < 8; i++) {
        const float linv = 1.f / sL[pr + i];
        float4 v0 = make_float4(acc[i][0] * linv, acc[i][1] * linv,
                                acc[i][2] * linv, acc[i][3] * linv);
        float4 v1 = make_float4(acc[i][4] * linv, acc[i][5] * linv,
                                acc[i][6] * linv, acc[i][7] * linv);
        *(float4*)(outp + (long long)(pr + i) * KL_ + pc)     = v0;
        *(float4*)(outp + (long long)(pr + i) * KL_ + pc + 4) = v1;
    }
}

// ------------------- launch ---------------------------------------------------
extern "C" void kernel_launch(void* const* d_in, const int* in_sizes, int n_in,
                              void* d_out, int out_size)
{
    const float* x      = (const float*)d_in[0];
    const float* w_qd   = (const float*)d_in[3];
    const float* b_qd   = (const float*)d_in[4];
    const float* gam_q  = (const float*)d_in[5];
    const float* w_qn   = (const float*)d_in[6];
    const float* b_qn   = (const float*)d_in[7];
    const float* w_qr   = (const float*)d_in[8];
    const float* b_qr   = (const float*)d_in[9];
    const float* w_kvd  = (const float*)d_in[10];
    const float* b_kvd  = (const float*)d_in[11];
    const float* gam_kv = (const float*)d_in[12];
    const float* w_ku   = (const float*)d_in[13];
    const float* w_vu   = (const float*)d_in[15];
    const float* w_kr   = (const float*)d_in[17];
    const float* b_kr   = (const float*)d_in[18];
    const float* gates  = (const float*)d_in[19];
    const float* w_o    = (const float*)d_in[20];
    const float* b_o    = (const float*)d_in[21];
    float* out = (float*)d_out;

    float *qc, *qnope, *qrope, *kvp, *krope, *qabs, *lat, *outhd;
    cudaGetSymbolAddress((void**)&qc,    g_qc);
    cudaGetSymbolAddress((void**)&qnope, g_qnope);
    cudaGetSymbolAddress((void**)&qrope, g_qrope);
    cudaGetSymbolAddress((void**)&kvp,   g_kv);
    cudaGetSymbolAddress((void**)&krope, g_krope);
    cudaGetSymbolAddress((void**)&qabs,  g_qabs);
    cudaGetSymbolAddress((void**)&lat,   g_lat);
    cudaGetSymbolAddress((void**)&outhd, g_outhd);

    const int smem_attn = (DK_ * 33 * 2 + 32 * 33 + 64) * sizeof(float);
    cudaFuncSetAttribute(mla_attn_kernel,
                         cudaFuncAttributeMaxDynamicSharedMemorySize, smem_attn);

    dim3 blk(256);
    // qc = x @ w_qd^T + b_qd ; rmsnorm
    gemm_kernel<true><<<dim3(QL_ / 128, MT / 128, 1), blk>>>(
        x, D_, 0, w_qd, D_, 0, qc, QL_, 0, QL_, D_, b_qd, nullptr);
    rmsnorm_kernel<<<MT, 128>>>(qc, gam_q, QL_);
    // q_nope = qc @ w_qn^T + b_qn
    gemm_kernel<true><<<dim3(D_ / 128, MT / 128, 1), blk>>>(
        qc, QL_, 0, w_qn, QL_, 0, qnope, D_, 0, D_, QL_, b_qn, nullptr);
    // q_rope = rope(qc @ w_qr^T + b_qr)
    gemm_kernel<true><<<dim3((H_ * RD_) / 128, MT / 128, 1), blk>>>(
        qc, QL_, 0, w_qr, QL_, 0, qrope, H_ * RD_, 0, H_ * RD_, QL_, b_qr, nullptr);
    rope_q_kernel<<<MT * H_ * 32 / 256, 256>>>(qrope);
    // kv = rmsnorm(x @ w_kvd^T + b_kvd)
    gemm_kernel<true><<<dim3(KL_ / 128, MT / 128, 1), blk>>>(
        x, D_, 0, w_kvd, D_, 0, kvp, KL_, 0, KL_, D_, b_kvd, nullptr);
    rmsnorm_kernel<<<MT, 128>>>(kvp, gam_kv, KL_);
    // k_rope = rope(x @ w_kr^T + b_kr)
    gemm_kernel<true><<<dim3(1, MT / 128, 1), blk>>>(
        x, D_, 0, w_kr, D_, 0, krope, RD_, 0, RD_, D_, b_kr, nullptr);
    rope_k_kernel<<<MT * 32 / 256, 256>>>(krope);
    // q_abs[h] = q_nope_h @ w_uk[h]   (B non-transposed, K=HD)
    gemm_kernel<false><<<dim3(KL_ / 128, MT / 128, H_), blk>>>(
        qnope, D_, HD_, w_ku, KL_, (long long)HD_ * KL_,
        qabs, KL_, (long long)MT * KL_, KL_, HD_, nullptr, nullptr);
    // attention
    mla_attn_kernel<<<dim3(S_ / 32, H_, B_), blk, smem_attn>>>(
        qabs, qrope, kvp, krope, lat);
    // out_h = (lat_h @ w_uv[h]^T) * sigmoid(gate[h])  (no bias)
    gemm_kernel<true><<<dim3(1, MT / 128, H_), blk>>>(
        lat, KL_, (long long)MT * KL_, w_vu, KL_, (long long)HD_ * KL_,
        outhd, D_, HD_, HD_, KL_, nullptr, gates);
    // final: out = outhd @ w_o^T + b_o
    gemm_kernel<true><<<dim3(D_ / 128, MT / 128, 1), blk>>>(
        outhd, D_, 0, w_o, D_, 0, out, D_, 0, D_, D_, b_o, nullptr);
}

// round 4
// speedup vs baseline: 2.5236x; 2.5236x over previous
#include <cuda_runtime.h>
#include <cuda_bf16.h>
#include <math.h>

#define B_  4
#define S_  2048
#define D_  2048
#define H_  16
#define HD_ 128
#define RD_ 64
#define QL_ 512
#define KL_ 512
#define MT  (B_*S_)
#define DK_ 576
#define SM_SCALE 0.07216878364870323f  // 1/sqrt(192)

// ------------------- scratch (device globals; no runtime allocs) ------------
__device__ float g_qc   [(size_t)MT * QL_];
__device__ float g_qnope[(size_t)MT * D_];
__device__ float g_qrope[(size_t)MT * (H_ * RD_)];
__device__ float g_kv   [(size_t)MT * KL_];
__device__ float g_krope[(size_t)MT * RD_];
__device__ float g_qabs [(size_t)H_ * MT * KL_];
__device__ float g_lat  [(size_t)H_ * MT * KL_];
__device__ float g_outhd[(size_t)MT * D_];

// ------------------- generic SGEMM (unchanged, passing) ----------------------
template<bool TRANSB>
__global__ __launch_bounds__(256) void gemm_kernel(
    const float* __restrict__ A, int lda, long long sAz,
    const float* __restrict__ B, int ldb, long long sBz,
    float* __restrict__ C, int ldc, long long sCz,
    int N, int K,
    const float* __restrict__ bias,
    const float* __restrict__ gates)
{
    __shared__ float sA[8][128];
    __shared__ float sB[8][128];
    const int z = blockIdx.z;
    A += (long long)z * sAz;  B += (long long)z * sBz;  C += (long long)z * sCz;

    const int tid = threadIdx.x;
    const int m0 = blockIdx.y * 128, n0 = blockIdx.x * 128;
    const int ty = tid >> 4, tx = tid & 15;
    const int am = tid >> 1;
    const int ak = (tid & 1) * 4;

    float acc[8][8];
#pragma unroll
    for (int i = 0; i < 8; i++)
#pragma unroll
        for (int j = 0; j < 8; j++) acc[i][j] = 0.f;

    for (int k0 = 0; k0 < K; k0 += 8) {
        float4 av = *(const float4*)(A + (long long)(m0 + am) * lda + (k0 + ak));
        if (TRANSB) {
            float4 bv = make_float4(0.f, 0.f, 0.f, 0.f);
            if (n0 + am < N)
                bv = *(const float4*)(B + (long long)(n0 + am) * ldb + (k0 + ak));
            sB[ak + 0][am] = bv.x; sB[ak + 1][am] = bv.y;
            sB[ak + 2][am] = bv.z; sB[ak + 3][am] = bv.w;
        } else {
            const int kb = (tid * 4) >> 7;
            const int nb = (tid * 4) & 127;
            float4 bv = make_float4(0.f, 0.f, 0.f, 0.f);
            if (n0 + nb < N)
                bv = *(const float4*)(B + (long long)(k0 + kb) * ldb + (n0 + nb));
            *(float4*)&sB[kb][nb] = bv;
        }
        sA[ak + 0][am] = av.x; sA[ak + 1][am] = av.y;
        sA[ak + 2][am] = av.z; sA[ak + 3][am] = av.w;
        __syncthreads();

#pragma unroll
        for (int kk = 0; kk < 8; kk++) {
            float a[8], b[8];
            *(float4*)(a)     = *(const float4*)&sA[kk][ty * 4];
            *(float4*)(a + 4) = *(const float4*)&sA[kk][64 + ty * 4];
            *(float4*)(b)     = *(const float4*)&sB[kk][tx * 4];
            *(float4*)(b + 4) = *(const float4*)&sB[kk][64 + tx * 4];
#pragma unroll
            for (int i = 0; i < 8; i++)
#pragma unroll
                for (int j = 0; j < 8; j++) acc[i][j] += a[i] * b[j];
        }
        __syncthreads();
    }

    float scale = 1.f;
    if (gates) scale = 1.f / (1.f + expf(-gates[z]));
#pragma unroll
    for (int i = 0; i < 8; i++) {
        const int m = m0 + ((i < 4) ? (ty * 4 + i) : (60 + ty * 4 + i));
#pragma unroll
        for (int j = 0; j < 8; j++) {
            const int n = n0 + ((j < 4) ? (tx * 4 + j) : (60 + tx * 4 + j));
            if (n < N) {
                float v = acc[i][j];
                if (bias) v += bias[n];
                C[(long long)m * ldc + n] = v * scale;
            }
        }
    }
}

// ------------------- rmsnorm (in place) --------------------------------------
__global__ void rmsnorm_kernel(float* __restrict__ data,
                               const float* __restrict__ gamma, int width)
{
    float* p = data + (long long)blockIdx.x * width;
    const int tid = threadIdx.x;
    float ss = 0.f;
    for (int i = tid * 4; i < width; i += 512) {
        float4 v = *(const float4*)(p + i);
        ss += v.x * v.x + v.y * v.y + v.z * v.z + v.w * v.w;
    }
#pragma unroll
    for (int off = 16; off; off >>= 1) ss += __shfl_xor_sync(~0u, ss, off);
    __shared__ float ws[4];
    if ((tid & 31) == 0) ws[tid >> 5] = ss;
    __syncthreads();
    const float inv = rsqrtf((ws[0] + ws[1] + ws[2] + ws[3]) / (float)width + 1e-6f);
    for (int i = tid * 4; i < width; i += 512) {
        float4 v = *(const float4*)(p + i);
        float4 g = *(const float4*)(gamma + i);
        v.x *= inv * g.x; v.y *= inv * g.y; v.z *= inv * g.z; v.w *= inv * g.w;
        *(float4*)(p + i) = v;
    }
}

// ------------------- RoPE (in place) -----------------------------------------
__device__ __forceinline__ void rope_pair(float* p, int i, int m)
{
    const float x1 = p[i], x2 = p[i + 32];
    const float pos = (float)(m & (S_ - 1));
    const float inv_freq = exp2f(-(float)i * (13.287712379549449f / 32.f));
    float sn, cs;
    sincosf(pos * inv_freq, &sn, &cs);
    p[i]      = x1 * cs - x2 * sn;
    p[i + 32] = x1 * sn + x2 * cs;
}

__global__ void rope_q_kernel(float* __restrict__ q)
{
    const int idx = blockIdx.x * 256 + threadIdx.x;
    const int i = idx & 31, rest = idx >> 5;
    const int h = rest & (H_ - 1), m = rest >> 4;
    rope_pair(q + (long long)m * (H_ * RD_) + h * RD_, i, m);
}

__global__ void rope_k_kernel(float* __restrict__ k)
{
    const int idx = blockIdx.x * 256 + threadIdx.x;
    const int i = idx & 31, m = idx >> 5;
    rope_pair(k + (long long)m * RD_, i, m);
}

// ------------------- tf32 mma helpers ----------------------------------------
__device__ __forceinline__ unsigned f2tf(float f)
{
    unsigned u; asm("cvt.rna.tf32.f32 %0, %1;" : "=r"(u) : "f"(f)); return u;
}
__device__ __forceinline__ void mma_tf32(float c[4],
    unsigned a0, unsigned a1, unsigned a2, unsigned a3,
    unsigned b0, unsigned b1)
{
    asm volatile("mma.sync.aligned.m16n8k8.row.col.f32.tf32.tf32.f32 "
                 "{%0,%1,%2,%3},{%4,%5,%6,%7},{%8,%9},{%0,%1,%2,%3};"
                 : "+f"(c[0]), "+f"(c[1]), "+f"(c[2]), "+f"(c[3])
                 : "r"(a0), "r"(a1), "r"(a2), "r"(a3), "r"(b0), "r"(b1));
}

// ------------------- tf32 tensor-core causal flash attention ------------------
// grid (S/32, H, B), 256 threads (8 warps). BM=32, BN=64.
// smem strides: 580 (4 mod 32 -> bank = 4*row+col, fragment loads conflict-free)
#define KSTR 580
#define PSTR 68
__global__ __launch_bounds__(256, 1) void mla_attn_kernel(
    const float* __restrict__ qabs,   // [H][MT][512]
    const float* __restrict__ qrope,  // [MT][H*64]
    const float* __restrict__ kv,     // [MT][512]
    const float* __restrict__ krope,  // [MT][64]
    float* __restrict__ lat)          // [H][MT][512]
{
    extern __shared__ float sm[];
    float* sQ     = sm;                    // [32][580] tf32 bits
    float* sK     = sQ + 32 * KSTR;        // [64][580] tf32 bits
    float* sP     = sK + 64 * KSTR;        // [32][68]  scores fp32 -> probs tf32
    float* sAlpha = sP + 32 * PSTR;        // [32]
    float* sL     = sAlpha + 32;           // [32]
    unsigned* uQ = (unsigned*)sQ;
    unsigned* uK = (unsigned*)sK;
    unsigned* uP = (unsigned*)sP;

    const int qt = blockIdx.x, h = blockIdx.y, b = blockIdx.z;
    const int tid = threadIdx.x;
    const int warp = tid >> 5, lane = tid & 31;
    const int gid = lane >> 2, tig = lane & 3;
    const long long mbase = (long long)b * S_;
    const int q0 = qt * 32;

    // ---- load Q tile (32 x 576), scaled is NOT applied here (applied in softmax)
    {
        const float* qa = qabs + ((long long)h * MT + mbase + q0) * KL_;
        for (int idx = tid; idx < 32 * 128; idx += 256) {
            const int r = idx >> 7, c4 = (idx & 127) * 4;
            float4 v = *(const float4*)(qa + (long long)r * KL_ + c4);
            unsigned* d = uQ + r * KSTR + c4;
            d[0] = f2tf(v.x); d[1] = f2tf(v.y); d[2] = f2tf(v.z); d[3] = f2tf(v.w);
        }
        const float* qr = qrope + (mbase + q0) * (H_ * RD_) + h * RD_;
        for (int idx = tid; idx < 32 * 16; idx += 256) {
            const int r = idx >> 4, c4 = (idx & 15) * 4;
            float4 v = *(const float4*)(qr + (long long)r * (H_ * RD_) + c4);
            unsigned* d = uQ + r * KSTR + KL_ + c4;
            d[0] = f2tf(v.x); d[1] = f2tf(v.y); d[2] = f2tf(v.z); d[3] = f2tf(v.w);
        }
    }

    // warp roles
    const int sm0 = (warp & 1) * 16;       // score rows (also PV rows)
    const int sn0 = (warp >> 1) * 16;      // score cols
    const int pc0 = (warp >> 1) * 128;     // PV col quarter

    // softmax ownership: thread -> row tid>>3, cols (tid&7)*8..+7
    const int srow = tid >> 3;
    const int scb  = (tid & 7) * 8;
    float m_run = -INFINITY, l_run = 0.f;

    float oc[16][4];
#pragma unroll
    for (int i = 0; i < 16; i++)
#pragma unroll
        for (int j = 0; j < 4; j++) oc[i][j] = 0.f;

    const int ntiles = (q0 + 31) / 64 + 1;
    for (int tt = 0; tt < ntiles; tt++) {
        const int t0 = tt * 64;
        __syncthreads();                   // prev PV done with sK/sP
        // ---- load K tile (64 x 576) as tf32
        {
            const float* kvp = kv + (mbase + t0) * KL_;
            for (int idx = tid; idx < 64 * 128; idx += 256) {
                const int r = idx >> 7, c4 = (idx & 127) * 4;
                float4 v = *(const float4*)(kvp + (long long)r * KL_ + c4);
                unsigned* d = uK + r * KSTR + c4;
                d[0] = f2tf(v.x); d[1] = f2tf(v.y); d[2] = f2tf(v.z); d[3] = f2tf(v.w);
            }
            const float* krp = krope + (mbase + t0) * RD_;
            for (int idx = tid; idx < 64 * 16; idx += 256) {
                const int r = idx >> 4, c4 = (idx & 15) * 4;
                float4 v = *(const float4*)(krp + (long long)r * RD_ + c4);
                unsigned* d = uK + r * KSTR + KL_ + c4;
                d[0] = f2tf(v.x); d[1] = f2tf(v.y); d[2] = f2tf(v.z); d[3] = f2tf(v.w);
            }
        }
        __syncthreads();

        // ---- score: warp computes m16 x n16 (two n8 subtiles)
        float c0[4] = {0.f, 0.f, 0.f, 0.f}, c1[4] = {0.f, 0.f, 0.f, 0.f};
        {
            const unsigned* qp0 = uQ + (sm0 + gid) * KSTR + tig;
            const unsigned* qp1 = uQ + (sm0 + gid + 8) * KSTR + tig;
            const unsigned* kp0 = uK + (sn0 + gid) * KSTR + tig;
            const unsigned* kp1 = uK + (sn0 + 8 + gid) * KSTR + tig;
#pragma unroll 4
            for (int kc = 0; kc < 72; kc++) {
                const int k = kc * 8;
                unsigned a0 = qp0[k], a1 = qp1[k], a2 = qp0[k + 4], a3 = qp1[k + 4];
                unsigned b0 = kp0[k], b1 = kp0[k + 4];
                mma_tf32(c0, a0, a1, a2, a3, b0, b1);
                unsigned b2 = kp1[k], b3 = kp1[k + 4];
                mma_tf32(c1, a0, a1, a2, a3, b2, b3);
            }
        }
        // write raw scores (fp32) to sP
        {
            float* p0 = sP + (sm0 + gid) * PSTR + sn0 + tig * 2;
            float* p1 = sP + (sm0 + gid + 8) * PSTR + sn0 + tig * 2;
            p0[0] = c0[0]; p0[1] = c0[1]; p1[0] = c0[2]; p1[1] = c0[3];
            p0[8] = c1[0]; p0[9] = c1[1]; p1[8] = c1[2]; p1[9] = c1[3];
        }
        __syncthreads();

        // ---- online softmax: 8 threads per row, 8 cols each
        {
            const int rglob = q0 + srow;
            float s[8];
            float4 v0 = *(const float4*)&sP[srow * PSTR + scb];
            float4 v1 = *(const float4*)&sP[srow * PSTR + scb + 4];
            s[0] = v0.x; s[1] = v0.y; s[2] = v0.z; s[3] = v0.w;
            s[4] = v1.x; s[5] = v1.y; s[6] = v1.z; s[7] = v1.w;
            float mx = -INFINITY;
#pragma unroll
            for (int j = 0; j < 8; j++) {
                s[j] = (t0 + scb + j <= rglob) ? s[j] * SM_SCALE : -INFINITY;
                mx = fmaxf(mx, s[j]);
            }
#pragma unroll
            for (int off = 1; off < 8; off <<= 1)
                mx = fmaxf(mx, __shfl_xor_sync(~0u, mx, off, 8));
            const float mnew = fmaxf(m_run, mx);
            const float alpha = expf(m_run - mnew);
            float lsum = 0.f;
#pragma unroll
            for (int j = 0; j < 8; j++) { s[j] = expf(s[j] - mnew); lsum += s[j]; }
#pragma unroll
            for (int off = 1; off < 8; off <<= 1)
                lsum += __shfl_xor_sync(~0u, lsum, off, 8);
            l_run = l_run * alpha + lsum;
            m_run = mnew;
            unsigned* d = uP + srow * PSTR + scb;
#pragma unroll
            for (int j = 0; j < 8; j++) d[j] = f2tf(s[j]);
            if ((tid & 7) == 0) sAlpha[srow] = alpha;
        }
        __syncthreads();

        // ---- PV: rescale then acc += P(32xk64) @ V(k64 x 128-quarter)
        {
            const float aL = sAlpha[sm0 + gid];
            const float aH = sAlpha[sm0 + gid + 8];
#pragma unroll
            for (int nt = 0; nt < 16; nt++) {
                oc[nt][0] *= aL; oc[nt][1] *= aL;
                oc[nt][2] *= aH; oc[nt][3] *= aH;
            }
#pragma unroll
            for (int kc = 0; kc < 8; kc++) {
                const int kk = kc * 8;
                unsigned pa0 = uP[(sm0 + gid) * PSTR + kk + tig];
                unsigned pa1 = uP[(sm0 + gid + 8) * PSTR + kk + tig];
                unsigned pa2 = uP[(sm0 + gid) * PSTR + kk + tig + 4];
                unsigned pa3 = uP[(sm0 + gid + 8) * PSTR + kk + tig + 4];
                const unsigned* v0 = uK + (kk + tig) * KSTR + pc0 + gid;
                const unsigned* v1 = uK + (kk + tig + 4) * KSTR + pc0 + gid;
#pragma unroll
                for (int nt = 0; nt < 16; nt++)
                    mma_tf32(oc[nt], pa0, pa1, pa2, pa3, v0[nt * 8], v1[nt * 8]);
            }
        }
    }

    // ---- epilogue: divide by l, store
    if ((tid & 7) == 0) sL[srow] = l_run;
    __syncthreads();
    const float invL = 1.f / sL[sm0 + gid];
    const float invH = 1.f / sL[sm0 + gid + 8];
    float* outp = lat + ((long long)h * MT + mbase + q0) * KL_;
#pragma unroll
    for (int nt = 0; nt < 16; nt++) {
        const int col = pc0 + nt * 8 + tig * 2;
        float2 w0 = make_float2(oc[nt][0] * invL, oc[nt][1] * invL);
        float2 w1 = make_float2(oc[nt][2] * invH, oc[nt][3] * invH);
        *(float2*)(outp + (long long)(sm0 + gid) * KL_ + col)     = w0;
        *(float2*)(outp + (long long)(sm0 + gid + 8) * KL_ + col) = w1;
    }
}

// ------------------- launch ---------------------------------------------------
extern "C" void kernel_launch(void* const* d_in, const int* in_sizes, int n_in,
                              void* d_out, int out_size)
{
    const float* x      = (const float*)d_in[0];
    const float* w_qd   = (const float*)d_in[3];
    const float* b_qd   = (const float*)d_in[4];
    const float* gam_q  = (const float*)d_in[5];
    const float* w_qn   = (const float*)d_in[6];
    const float* b_qn   = (const float*)d_in[7];
    const float* w_qr   = (const float*)d_in[8];
    const float* b_qr   = (const float*)d_in[9];
    const float* w_kvd  = (const float*)d_in[10];
    const float* b_kvd  = (const float*)d_in[11];
    const float* gam_kv = (const float*)d_in[12];
    const float* w_ku   = (const float*)d_in[13];
    const float* w_vu   = (const float*)d_in[15];
    const float* w_kr   = (const float*)d_in[17];
    const float* b_kr   = (const float*)d_in[18];
    const float* gates  = (const float*)d_in[19];
    const float* w_o    = (const float*)d_in[20];
    const float* b_o    = (const float*)d_in[21];
    float* out = (float*)d_out;

    float *qc, *qnope, *qrope, *kvp, *krope, *qabs, *lat, *outhd;
    cudaGetSymbolAddress((void**)&qc,    g_qc);
    cudaGetSymbolAddress((void**)&qnope, g_qnope);
    cudaGetSymbolAddress((void**)&qrope, g_qrope);
    cudaGetSymbolAddress((void**)&kvp,   g_kv);
    cudaGetSymbolAddress((void**)&krope, g_krope);
    cudaGetSymbolAddress((void**)&qabs,  g_qabs);
    cudaGetSymbolAddress((void**)&lat,   g_lat);
    cudaGetSymbolAddress((void**)&outhd, g_outhd);

    const int smem_attn = (32 * KSTR + 64 * KSTR + 32 * PSTR + 64) * sizeof(float);
    cudaFuncSetAttribute(mla_attn_kernel,
                         cudaFuncAttributeMaxDynamicSharedMemorySize, smem_attn);

    dim3 blk(256);
    gemm_kernel<true><<<dim3(QL_ / 128, MT / 128, 1), blk>>>(
        x, D_, 0, w_qd, D_, 0, qc, QL_, 0, QL_, D_, b_qd, nullptr);
    rmsnorm_kernel<<<MT, 128>>>(qc, gam_q, QL_);
    gemm_kernel<true><<<dim3(D_ / 128, MT / 128, 1), blk>>>(
        qc, QL_, 0, w_qn, QL_, 0, qnope, D_, 0, D_, QL_, b_qn, nullptr);
    gemm_kernel<true><<<dim3((H_ * RD_) / 128, MT / 128, 1), blk>>>(
        qc, QL_, 0, w_qr, QL_, 0, qrope, H_ * RD_, 0, H_ * RD_, QL_, b_qr, nullptr);
    rope_q_kernel<<<MT * H_ * 32 / 256, 256>>>(qrope);
    gemm_kernel<true><<<dim3(KL_ / 128, MT / 128, 1), blk>>>(
        x, D_, 0, w_kvd, D_, 0, kvp, KL_, 0, KL_, D_, b_kvd, nullptr);
    rmsnorm_kernel<<<MT, 128>>>(kvp, gam_kv, KL_);
    gemm_kernel<true><<<dim3(1, MT / 128, 1), blk>>>(
        x, D_, 0, w_kr, D_, 0, krope, RD_, 0, RD_, D_, b_kr, nullptr);
    rope_k_kernel<<<MT * 32 / 256, 256>>>(krope);
    gemm_kernel<false><<<dim3(KL_ / 128, MT / 128, H_), blk>>>(
        qnope, D_, HD_, w_ku, KL_, (long long)HD_ * KL_,
        qabs, KL_, (long long)MT * KL_, KL_, HD_, nullptr, nullptr);
    mla_attn_kernel<<<dim3(S_ / 32, H_, B_), blk, smem_attn>>>(
        qabs, qrope, kvp, krope, lat);
    gemm_kernel<true><<<dim3(1, MT / 128, H_), blk>>>(
        lat, KL_, (long long)MT * KL_, w_vu, KL_, (long long)HD_ * KL_,
        outhd, D_, HD_, HD_, KL_, nullptr, gates);
    gemm_kernel<true><<<dim3(D_ / 128, MT / 128, 1), blk>>>(
        outhd, D_, 0, w_o, D_, 0, out, D_, 0, D_, D_, b_o, nullptr);
}

// round 5
// speedup vs baseline: 3.7036x; 1.4676x over previous
#include <cuda_runtime.h>
#include <cuda_bf16.h>
#include <math.h>

#define B_  4
#define S_  2048
#define D_  2048
#define H_  16
#define HD_ 128
#define RD_ 64
#define QL_ 512
#define KL_ 512
#define MT  (B_*S_)
#define DK_ 576
#define SM_SCALE 0.07216878364870323f  // 1/sqrt(192)

// ------------------- scratch (device globals; no runtime allocs) ------------
__device__ float g_qc   [(size_t)MT * QL_];
__device__ float g_qnope[(size_t)MT * D_];
__device__ float g_qrope[(size_t)MT * (H_ * RD_)];
__device__ float g_kv   [(size_t)MT * KL_];
__device__ float g_krope[(size_t)MT * RD_];
__device__ float g_qabs [(size_t)H_ * MT * KL_];
__device__ float g_lat  [(size_t)H_ * MT * KL_];
__device__ float g_outhd[(size_t)MT * D_];

// ------------------- tf32 mma helpers ----------------------------------------
__device__ __forceinline__ unsigned f2tf(float f)
{
    unsigned u; asm("cvt.rna.tf32.f32 %0, %1;" : "=r"(u) : "f"(f)); return u;
}
__device__ __forceinline__ void mma_tf32(float c[4],
    unsigned a0, unsigned a1, unsigned a2, unsigned a3,
    unsigned b0, unsigned b1)
{
    asm volatile("mma.sync.aligned.m16n8k8.row.col.f32.tf32.tf32.f32 "
                 "{%0,%1,%2,%3},{%4,%5,%6,%7},{%8,%9},{%0,%1,%2,%3};"
                 : "+f"(c[0]), "+f"(c[1]), "+f"(c[2]), "+f"(c[3])
                 : "r"(a0), "r"(a1), "r"(a2), "r"(a3), "r"(b0), "r"(b1));
}

// ------------------- tf32 tensor-core GEMM ------------------------------------
// C[M,N] = A @ B(^T) (+bias) (*sigmoid(gates[z])).
// 128x128 block tile, BK=32, 256 threads (8 warps), warp = 32x64 (2x8 mmas).
// Tiles stored [row][k] with stride 36 (=4 mod 32) -> fragment loads conflict-free.
#define GKS 36
template<bool TRANSB>
__global__ __launch_bounds__(256) void gemm_tf32(
    const float* __restrict__ A, int lda, long long sAz,
    const float* __restrict__ B, int ldb, long long sBz,
    float* __restrict__ C, int ldc, long long sCz,
    int N, int K,
    const float* __restrict__ bias,
    const float* __restrict__ gates)
{
    __shared__ unsigned sA[128 * GKS];
    __shared__ unsigned sB[128 * GKS];

    const int z = blockIdx.z;
    A += (long long)z * sAz;  B += (long long)z * sBz;  C += (long long)z * sCz;

    const int tid = threadIdx.x;
    const int warp = tid >> 5, lane = tid & 31;
    const int gid = lane >> 2, tig = lane & 3;
    const int m0 = blockIdx.y * 128, n0 = blockIdx.x * 128;
    const int wm = (warp & 3) * 32;        // warp m offset (0,32,64,96)
    const int wn = (warp >> 2) * 64;       // warp n offset (0,64)

    float acc[2][8][4];
#pragma unroll
    for (int mt = 0; mt < 2; mt++)
#pragma unroll
        for (int nt = 0; nt < 8; nt++)
#pragma unroll
            for (int j = 0; j < 4; j++) acc[mt][nt][j] = 0.f;

    for (int k0 = 0; k0 < K; k0 += 32) {
        // A tile: 128 x 32 floats as float4
#pragma unroll
        for (int i = 0; i < 4; i++) {
            const int lin = tid + i * 256;             // 0..1023
            const int r = lin >> 3, c4 = (lin & 7) * 4;
            float4 v = *(const float4*)(A + (long long)(m0 + r) * lda + k0 + c4);
            unsigned* d = sA + r * GKS + c4;
            d[0] = f2tf(v.x); d[1] = f2tf(v.y); d[2] = f2tf(v.z); d[3] = f2tf(v.w);
        }
        if (TRANSB) {
#pragma unroll
            for (int i = 0; i < 4; i++) {
                const int lin = tid + i * 256;
                const int r = lin >> 3, c4 = (lin & 7) * 4;
                float4 v = make_float4(0.f, 0.f, 0.f, 0.f);
                if (n0 + r < N)
                    v = *(const float4*)(B + (long long)(n0 + r) * ldb + k0 + c4);
                unsigned* d = sB + r * GKS + c4;
                d[0] = f2tf(v.x); d[1] = f2tf(v.y); d[2] = f2tf(v.z); d[3] = f2tf(v.w);
            }
        } else {
            // B is [K,N] row-major; sB[n][k] ; coalesced along n
#pragma unroll
            for (int i = 0; i < 16; i++) {
                const int lin = tid + i * 256;         // 0..4095
                const int n = lin & 127, k = lin >> 7; // k 0..31
                float v = (n0 + n < N) ? B[(long long)(k0 + k) * ldb + n0 + n] : 0.f;
                sB[n * GKS + k] = f2tf(v);
            }
        }
        __syncthreads();

#pragma unroll
        for (int kk = 0; kk < 4; kk++) {
            const int k8 = kk * 8;
            unsigned a[2][4], b[8][2];
#pragma unroll
            for (int mt = 0; mt < 2; mt++) {
                const unsigned* p = sA + (wm + mt * 16 + gid) * GKS + k8 + tig;
                a[mt][0] = p[0];
                a[mt][1] = p[8 * GKS];
                a[mt][2] = p[4];
                a[mt][3] = p[8 * GKS + 4];
            }
#pragma unroll
            for (int nt = 0; nt < 8; nt++) {
                const unsigned* p = sB + (wn + nt * 8 + gid) * GKS + k8 + tig;
                b[nt][0] = p[0];
                b[nt][1] = p[4];
            }
#pragma unroll
            for (int mt = 0; mt < 2; mt++)
#pragma unroll
                for (int nt = 0; nt < 8; nt++)
                    mma_tf32(acc[mt][nt], a[mt][0], a[mt][1], a[mt][2], a[mt][3],
                             b[nt][0], b[nt][1]);
        }
        __syncthreads();
    }

    float scale = 1.f;
    if (gates) scale = 1.f / (1.f + expf(-gates[z]));
#pragma unroll
    for (int mt = 0; mt < 2; mt++) {
        const int r0 = m0 + wm + mt * 16 + gid;
#pragma unroll
        for (int nt = 0; nt < 8; nt++) {
            const int col = n0 + wn + nt * 8 + tig * 2;
            if (col < N) {
                float bx = 0.f, by = 0.f;
                if (bias) { bx = bias[col]; by = bias[col + 1]; }
                float2 w0 = make_float2((acc[mt][nt][0] + bx) * scale,
                                        (acc[mt][nt][1] + by) * scale);
                float2 w1 = make_float2((acc[mt][nt][2] + bx) * scale,
                                        (acc[mt][nt][3] + by) * scale);
                *(float2*)(C + (long long)r0 * ldc + col)       = w0;
                *(float2*)(C + (long long)(r0 + 8) * ldc + col) = w1;
            }
        }
    }
}

// ------------------- rmsnorm (in place) --------------------------------------
__global__ void rmsnorm_kernel(float* __restrict__ data,
                               const float* __restrict__ gamma, int width)
{
    float* p = data + (long long)blockIdx.x * width;
    const int tid = threadIdx.x;
    float ss = 0.f;
    for (int i = tid * 4; i < width; i += 512) {
        float4 v = *(const float4*)(p + i);
        ss += v.x * v.x + v.y * v.y + v.z * v.z + v.w * v.w;
    }
#pragma unroll
    for (int off = 16; off; off >>= 1) ss += __shfl_xor_sync(~0u, ss, off);
    __shared__ float ws[4];
    if ((tid & 31) == 0) ws[tid >> 5] = ss;
    __syncthreads();
    const float inv = rsqrtf((ws[0] + ws[1] + ws[2] + ws[3]) / (float)width + 1e-6f);
    for (int i = tid * 4; i < width; i += 512) {
        float4 v = *(const float4*)(p + i);
        float4 g = *(const float4*)(gamma + i);
        v.x *= inv * g.x; v.y *= inv * g.y; v.z *= inv * g.z; v.w *= inv * g.w;
        *(float4*)(p + i) = v;
    }
}

// ------------------- RoPE (in place) -----------------------------------------
__device__ __forceinline__ void rope_pair(float* p, int i, int m)
{
    const float x1 = p[i], x2 = p[i + 32];
    const float pos = (float)(m & (S_ - 1));
    const float inv_freq = exp2f(-(float)i * (13.287712379549449f / 32.f));
    float sn, cs;
    sincosf(pos * inv_freq, &sn, &cs);
    p[i]      = x1 * cs - x2 * sn;
    p[i + 32] = x1 * sn + x2 * cs;
}

__global__ void rope_q_kernel(float* __restrict__ q)
{
    const int idx = blockIdx.x * 256 + threadIdx.x;
    const int i = idx & 31, rest = idx >> 5;
    const int h = rest & (H_ - 1), m = rest >> 4;
    rope_pair(q + (long long)m * (H_ * RD_) + h * RD_, i, m);
}

__global__ void rope_k_kernel(float* __restrict__ k)
{
    const int idx = blockIdx.x * 256 + threadIdx.x;
    const int i = idx & 31, m = idx >> 5;
    rope_pair(k + (long long)m * RD_, i, m);
}

// ------------------- tf32 tensor-core causal flash attention ------------------
// grid (S/32, H, B), 256 threads (8 warps). BM=32, BN=64.
#define KSTR 580
#define PSTR 68
__global__ __launch_bounds__(256, 1) void mla_attn_kernel(
    const float* __restrict__ qabs,   // [H][MT][512]
    const float* __restrict__ qrope,  // [MT][H*64]
    const float* __restrict__ kv,     // [MT][512]
    const float* __restrict__ krope,  // [MT][64]
    float* __restrict__ lat)          // [H][MT][512]
{
    extern __shared__ float sm[];
    float* sQ     = sm;
    float* sK     = sQ + 32 * KSTR;
    float* sP     = sK + 64 * KSTR;
    float* sAlpha = sP + 32 * PSTR;
    float* sL     = sAlpha + 32;
    unsigned* uQ = (unsigned*)sQ;
    unsigned* uK = (unsigned*)sK;
    unsigned* uP = (unsigned*)sP;

    const int qt = blockIdx.x, h = blockIdx.y, b = blockIdx.z;
    const int tid = threadIdx.x;
    const int warp = tid >> 5, lane = tid & 31;
    const int gid = lane >> 2, tig = lane & 3;
    const long long mbase = (long long)b * S_;
    const int q0 = qt * 32;

    {
        const float* qa = qabs + ((long long)h * MT + mbase + q0) * KL_;
        for (int idx = tid; idx < 32 * 128; idx += 256) {
            const int r = idx >> 7, c4 = (idx & 127) * 4;
            float4 v = *(const float4*)(qa + (long long)r * KL_ + c4);
            unsigned* d = uQ + r * KSTR + c4;
            d[0] = f2tf(v.x); d[1] = f2tf(v.y); d[2] = f2tf(v.z); d[3] = f2tf(v.w);
        }
        const float* qr = qrope + (mbase + q0) * (H_ * RD_) + h * RD_;
        for (int idx = tid; idx < 32 * 16; idx += 256) {
            const int r = idx >> 4, c4 = (idx & 15) * 4;
            float4 v = *(const float4*)(qr + (long long)r * (H_ * RD_) + c4);
            unsigned* d = uQ + r * KSTR + KL_ + c4;
            d[0] = f2tf(v.x); d[1] = f2tf(v.y); d[2] = f2tf(v.z); d[3] = f2tf(v.w);
        }
    }

    const int sm0 = (warp & 1) * 16;
    const int sn0 = (warp >> 1) * 16;
    const int pc0 = (warp >> 1) * 128;

    const int srow = tid >> 3;
    const int scb  = (tid & 7) * 8;
    float m_run = -INFINITY, l_run = 0.f;

    float oc[16][4];
#pragma unroll
    for (int i = 0; i < 16; i++)
#pragma unroll
        for (int j = 0; j < 4; j++) oc[i][j] = 0.f;

    const int ntiles = (q0 + 31) / 64 + 1;
    for (int tt = 0; tt < ntiles; tt++) {
        const int t0 = tt * 64;
        __syncthreads();
        {
            const float* kvp = kv + (mbase + t0) * KL_;
            for (int idx = tid; idx < 64 * 128; idx += 256) {
                const int r = idx >> 7, c4 = (idx & 127) * 4;
                float4 v = *(const float4*)(kvp + (long long)r * KL_ + c4);
                unsigned* d = uK + r * KSTR + c4;
                d[0] = f2tf(v.x); d[1] = f2tf(v.y); d[2] = f2tf(v.z); d[3] = f2tf(v.w);
            }
            const float* krp = krope + (mbase + t0) * RD_;
            for (int idx = tid; idx < 64 * 16; idx += 256) {
                const int r = idx >> 4, c4 = (idx & 15) * 4;
                float4 v = *(const float4*)(krp + (long long)r * RD_ + c4);
                unsigned* d = uK + r * KSTR + KL_ + c4;
                d[0] = f2tf(v.x); d[1] = f2tf(v.y); d[2] = f2tf(v.z); d[3] = f2tf(v.w);
            }
        }
        __syncthreads();

        float c0[4] = {0.f, 0.f, 0.f, 0.f}, c1[4] = {0.f, 0.f, 0.f, 0.f};
        {
            const unsigned* qp0 = uQ + (sm0 + gid) * KSTR + tig;
            const unsigned* qp1 = uQ + (sm0 + gid + 8) * KSTR + tig;
            const unsigned* kp0 = uK + (sn0 + gid) * KSTR + tig;
            const unsigned* kp1 = uK + (sn0 + 8 + gid) * KSTR + tig;
#pragma unroll 4
            for (int kc = 0; kc < 72; kc++) {
                const int k = kc * 8;
                unsigned a0 = qp0[k], a1 = qp1[k], a2 = qp0[k + 4], a3 = qp1[k + 4];
                unsigned b0 = kp0[k], b1 = kp0[k + 4];
                mma_tf32(c0, a0, a1, a2, a3, b0, b1);
                unsigned b2 = kp1[k], b3 = kp1[k + 4];
                mma_tf32(c1, a0, a1, a2, a3, b2, b3);
            }
        }
        {
            float* p0 = sP + (sm0 + gid) * PSTR + sn0 + tig * 2;
            float* p1 = sP + (sm0 + gid + 8) * PSTR + sn0 + tig * 2;
            p0[0] = c0[0]; p0[1] = c0[1]; p1[0] = c0[2]; p1[1] = c0[3];
            p0[8] = c1[0]; p0[9] = c1[1]; p1[8] = c1[2]; p1[9] = c1[3];
        }
        __syncthreads();

        {
            const int rglob = q0 + srow;
            float s[8];
            float4 v0 = *(const float4*)&sP[srow * PSTR + scb];
            float4 v1 = *(const float4*)&sP[srow * PSTR + scb + 4];
            s[0] = v0.x; s[1] = v0.y; s[2] = v0.z; s[3] = v0.w;
            s[4] = v1.x; s[5] = v1.y; s[6] = v1.z; s[7] = v1.w;
            float mx = -INFINITY;
#pragma unroll
            for (int j = 0; j < 8; j++) {
                s[j] = (t0 + scb + j <= rglob) ? s[j] * SM_SCALE : -INFINITY;
                mx = fmaxf(mx, s[j]);
            }
#pragma unroll
            for (int off = 1; off < 8; off <<= 1)
                mx = fmaxf(mx, __shfl_xor_sync(~0u, mx, off, 8));
            const float mnew = fmaxf(m_run, mx);
            const float alpha = expf(m_run - mnew);
            float lsum = 0.f;
#pragma unroll
            for (int j = 0; j < 8; j++) { s[j] = expf(s[j] - mnew); lsum += s[j]; }
#pragma unroll
            for (int off = 1; off < 8; off <<= 1)
                lsum += __shfl_xor_sync(~0u, lsum, off, 8);
            l_run = l_run * alpha + lsum;
            m_run = mnew;
            unsigned* d = uP + srow * PSTR + scb;
#pragma unroll
            for (int j = 0; j < 8; j++) d[j] = f2tf(s[j]);
            if ((tid & 7) == 0) sAlpha[srow] = alpha;
        }
        __syncthreads();

        {
            const float aL = sAlpha[sm0 + gid];
            const float aH = sAlpha[sm0 + gid + 8];
#pragma unroll
            for (int nt = 0; nt < 16; nt++) {
                oc[nt][0] *= aL; oc[nt][1] *= aL;
                oc[nt][2] *= aH; oc[nt][3] *= aH;
            }
#pragma unroll
            for (int kc = 0; kc < 8; kc++) {
                const int kk = kc * 8;
                unsigned pa0 = uP[(sm0 + gid) * PSTR + kk + tig];
                unsigned pa1 = uP[(sm0 + gid + 8) * PSTR + kk + tig];
                unsigned pa2 = uP[(sm0 + gid) * PSTR + kk + tig + 4];
                unsigned pa3 = uP[(sm0 + gid + 8) * PSTR + kk + tig + 4];
                const unsigned* v0 = uK + (kk + tig) * KSTR + pc0 + gid;
                const unsigned* v1 = uK + (kk + tig + 4) * KSTR + pc0 + gid;
#pragma unroll
                for (int nt = 0; nt < 16; nt++)
                    mma_tf32(oc[nt], pa0, pa1, pa2, pa3, v0[nt * 8], v1[nt * 8]);
            }
        }
    }

    if ((tid & 7) == 0) sL[srow] = l_run;
    __syncthreads();
    const float invL = 1.f / sL[sm0 + gid];
    const float invH = 1.f / sL[sm0 + gid + 8];
    float* outp = lat + ((long long)h * MT + mbase + q0) * KL_;
#pragma unroll
    for (int nt = 0; nt < 16; nt++) {
        const int col = pc0 + nt * 8 + tig * 2;
        float2 w0 = make_float2(oc[nt][0] * invL, oc[nt][1] * invL);
        float2 w1 = make_float2(oc[nt][2] * invH, oc[nt][3] * invH);
        *(float2*)(outp + (long long)(sm0 + gid) * KL_ + col)     = w0;
        *(float2*)(outp + (long long)(sm0 + gid + 8) * KL_ + col) = w1;
    }
}

// ------------------- launch ---------------------------------------------------
extern "C" void kernel_launch(void* const* d_in, const int* in_sizes, int n_in,
                              void* d_out, int out_size)
{
    const float* x      = (const float*)d_in[0];
    const float* w_qd   = (const float*)d_in[3];
    const float* b_qd   = (const float*)d_in[4];
    const float* gam_q  = (const float*)d_in[5];
    const float* w_qn   = (const float*)d_in[6];
    const float* b_qn   = (const float*)d_in[7];
    const float* w_qr   = (const float*)d_in[8];
    const float* b_qr   = (const float*)d_in[9];
    const float* w_kvd  = (const float*)d_in[10];
    const float* b_kvd  = (const float*)d_in[11];
    const float* gam_kv = (const float*)d_in[12];
    const float* w_ku   = (const float*)d_in[13];
    const float* w_vu   = (const float*)d_in[15];
    const float* w_kr   = (const float*)d_in[17];
    const float* b_kr   = (const float*)d_in[18];
    const float* gates  = (const float*)d_in[19];
    const float* w_o    = (const float*)d_in[20];
    const float* b_o    = (const float*)d_in[21];
    float* out = (float*)d_out;

    float *qc, *qnope, *qrope, *kvp, *krope, *qabs, *lat, *outhd;
    cudaGetSymbolAddress((void**)&qc,    g_qc);
    cudaGetSymbolAddress((void**)&qnope, g_qnope);
    cudaGetSymbolAddress((void**)&qrope, g_qrope);
    cudaGetSymbolAddress((void**)&kvp,   g_kv);
    cudaGetSymbolAddress((void**)&krope, g_krope);
    cudaGetSymbolAddress((void**)&qabs,  g_qabs);
    cudaGetSymbolAddress((void**)&lat,   g_lat);
    cudaGetSymbolAddress((void**)&outhd, g_outhd);

    const int smem_attn = (32 * KSTR + 64 * KSTR + 32 * PSTR + 64) * sizeof(float);
    cudaFuncSetAttribute(mla_attn_kernel,
                         cudaFuncAttributeMaxDynamicSharedMemorySize, smem_attn);

    dim3 blk(256);
    gemm_tf32<true><<<dim3(QL_ / 128, MT / 128, 1), blk>>>(
        x, D_, 0, w_qd, D_, 0, qc, QL_, 0, QL_, D_, b_qd, nullptr);
    rmsnorm_kernel<<<MT, 128>>>(qc, gam_q, QL_);
    gemm_tf32<true><<<dim3(D_ / 128, MT / 128, 1), blk>>>(
        qc, QL_, 0, w_qn, QL_, 0, qnope, D_, 0, D_, QL_, b_qn, nullptr);
    gemm_tf32<true><<<dim3((H_ * RD_) / 128, MT / 128, 1), blk>>>(
        qc, QL_, 0, w_qr, QL_, 0, qrope, H_ * RD_, 0, H_ * RD_, QL_, b_qr, nullptr);
    rope_q_kernel<<<MT * H_ * 32 / 256, 256>>>(qrope);
    gemm_tf32<true><<<dim3(KL_ / 128, MT / 128, 1), blk>>>(
        x, D_, 0, w_kvd, D_, 0, kvp, KL_, 0, KL_, D_, b_kvd, nullptr);
    rmsnorm_kernel<<<MT, 128>>>(kvp, gam_kv, KL_);
    gemm_tf32<true><<<dim3(1, MT / 128, 1), blk>>>(
        x, D_, 0, w_kr, D_, 0, krope, RD_, 0, RD_, D_, b_kr, nullptr);
    rope_k_kernel<<<MT * 32 / 256, 256>>>(krope);
    gemm_tf32<false><<<dim3(KL_ / 128, MT / 128, H_), blk>>>(
        qnope, D_, HD_, w_ku, KL_, (long long)HD_ * KL_,
        qabs, KL_, (long long)MT * KL_, KL_, HD_, nullptr, nullptr);
    mla_attn_kernel<<<dim3(S_ / 32, H_, B_), blk, smem_attn>>>(
        qabs, qrope, kvp, krope, lat);
    gemm_tf32<true><<<dim3(1, MT / 128, H_), blk>>>(
        lat, KL_, (long long)MT * KL_, w_vu, KL_, (long long)HD_ * KL_,
        outhd, D_, HD_, HD_, KL_, nullptr, gates);
    gemm_tf32<true><<<dim3(D_ / 128, MT / 128, 1), blk>>>(
        outhd, D_, 0, w_o, D_, 0, out, D_, 0, D_, D_, b_o, nullptr);
}

// round 7
// speedup vs baseline: 4.2377x; 1.1442x over previous
#include <cuda_runtime.h>
#include <cuda_bf16.h>
#include <math.h>

#define B_  4
#define S_  2048
#define D_  2048
#define H_  16
#define HD_ 128
#define RD_ 64
#define QL_ 512
#define KL_ 512
#define MT  (B_*S_)
#define DK_ 576
#define SM_SCALE 0.07216878364870323f  // 1/sqrt(192)

// ------------------- scratch (device globals; no runtime allocs) ------------
__device__ float g_qc   [(size_t)MT * QL_];
__device__ float g_qnope[(size_t)MT * D_];
__device__ float g_qrope[(size_t)MT * (H_ * RD_)];
__device__ float g_kv   [(size_t)MT * KL_];
__device__ float g_krope[(size_t)MT * RD_];
__device__ float g_qabs [(size_t)H_ * MT * KL_];
__device__ float g_lat  [(size_t)H_ * MT * KL_];
__device__ float g_outhd[(size_t)MT * D_];

// ------------------- tf32 mma helpers ----------------------------------------
__device__ __forceinline__ unsigned f2tf(float f)
{
    unsigned u; asm("cvt.rna.tf32.f32 %0, %1;" : "=r"(u) : "f"(f)); return u;
}
__device__ __forceinline__ void mma_tf32(float c[4],
    unsigned a0, unsigned a1, unsigned a2, unsigned a3,
    unsigned b0, unsigned b1)
{
    asm volatile("mma.sync.aligned.m16n8k8.row.col.f32.tf32.tf32.f32 "
                 "{%0,%1,%2,%3},{%4,%5,%6,%7},{%8,%9},{%0,%1,%2,%3};"
                 : "+f"(c[0]), "+f"(c[1]), "+f"(c[2]), "+f"(c[3])
                 : "r"(a0), "r"(a1), "r"(a2), "r"(a3), "r"(b0), "r"(b1));
}

// ------------------- tf32 tensor-core GEMM ------------------------------------
// C[M,N] = ((A @ B(^T)) + bias) * sigmoid(gates[z]) * uscale, opt tf32-rounded.
#define GKS 36
template<bool TRANSB>
__global__ __launch_bounds__(256) void gemm_tf32(
    const float* __restrict__ A, int lda, long long sAz,
    const float* __restrict__ B, int ldb, long long sBz,
    float* __restrict__ C, int ldc, long long sCz,
    int N, int K,
    const float* __restrict__ bias,
    const float* __restrict__ gates,
    float uscale, int tf32out)
{
    __shared__ unsigned sA[128 * GKS];
    __shared__ unsigned sB[128 * GKS];

    const int z = blockIdx.z;
    A += (long long)z * sAz;  B += (long long)z * sBz;  C += (long long)z * sCz;

    const int tid = threadIdx.x;
    const int warp = tid >> 5, lane = tid & 31;
    const int gid = lane >> 2, tig = lane & 3;
    const int m0 = blockIdx.y * 128, n0 = blockIdx.x * 128;
    const int wm = (warp & 3) * 32;
    const int wn = (warp >> 2) * 64;

    float acc[2][8][4];
#pragma unroll
    for (int mt = 0; mt < 2; mt++)
#pragma unroll
        for (int nt = 0; nt < 8; nt++)
#pragma unroll
            for (int j = 0; j < 4; j++) acc[mt][nt][j] = 0.f;

    for (int k0 = 0; k0 < K; k0 += 32) {
#pragma unroll
        for (int i = 0; i < 4; i++) {
            const int lin = tid + i * 256;
            const int r = lin >> 3, c4 = (lin & 7) * 4;
            float4 v = *(const float4*)(A + (long long)(m0 + r) * lda + k0 + c4);
            unsigned* d = sA + r * GKS + c4;
            d[0] = f2tf(v.x); d[1] = f2tf(v.y); d[2] = f2tf(v.z); d[3] = f2tf(v.w);
        }
        if (TRANSB) {
#pragma unroll
            for (int i = 0; i < 4; i++) {
                const int lin = tid + i * 256;
                const int r = lin >> 3, c4 = (lin & 7) * 4;
                float4 v = make_float4(0.f, 0.f, 0.f, 0.f);
                if (n0 + r < N)
                    v = *(const float4*)(B + (long long)(n0 + r) * ldb + k0 + c4);
                unsigned* d = sB + r * GKS + c4;
                d[0] = f2tf(v.x); d[1] = f2tf(v.y); d[2] = f2tf(v.z); d[3] = f2tf(v.w);
            }
        } else {
#pragma unroll
            for (int i = 0; i < 16; i++) {
                const int lin = tid + i * 256;
                const int n = lin & 127, k = lin >> 7;
                float v = (n0 + n < N) ? B[(long long)(k0 + k) * ldb + n0 + n] : 0.f;
                sB[n * GKS + k] = f2tf(v);
            }
        }
        __syncthreads();

#pragma unroll
        for (int kk = 0; kk < 4; kk++) {
            const int k8 = kk * 8;
            unsigned a[2][4], b[8][2];
#pragma unroll
            for (int mt = 0; mt < 2; mt++) {
                const unsigned* p = sA + (wm + mt * 16 + gid) * GKS + k8 + tig;
                a[mt][0] = p[0];
                a[mt][1] = p[8 * GKS];
                a[mt][2] = p[4];
                a[mt][3] = p[8 * GKS + 4];
            }
#pragma unroll
            for (int nt = 0; nt < 8; nt++) {
                const unsigned* p = sB + (wn + nt * 8 + gid) * GKS + k8 + tig;
                b[nt][0] = p[0];
                b[nt][1] = p[4];
            }
#pragma unroll
            for (int mt = 0; mt < 2; mt++)
#pragma unroll
                for (int nt = 0; nt < 8; nt++)
                    mma_tf32(acc[mt][nt], a[mt][0], a[mt][1], a[mt][2], a[mt][3],
                             b[nt][0], b[nt][1]);
        }
        __syncthreads();
    }

    float scale = uscale;
    if (gates) scale *= 1.f / (1.f + expf(-gates[z]));
#pragma unroll
    for (int mt = 0; mt < 2; mt++) {
        const int r0 = m0 + wm + mt * 16 + gid;
#pragma unroll
        for (int nt = 0; nt < 8; nt++) {
            const int col = n0 + wn + nt * 8 + tig * 2;
            if (col < N) {
                float bx = 0.f, by = 0.f;
                if (bias) { bx = bias[col]; by = bias[col + 1]; }
                float v00 = (acc[mt][nt][0] + bx) * scale;
                float v01 = (acc[mt][nt][1] + by) * scale;
                float v10 = (acc[mt][nt][2] + bx) * scale;
                float v11 = (acc[mt][nt][3] + by) * scale;
                if (tf32out) {
                    v00 = __uint_as_float(f2tf(v00));
                    v01 = __uint_as_float(f2tf(v01));
                    v10 = __uint_as_float(f2tf(v10));
                    v11 = __uint_as_float(f2tf(v11));
                }
                *(float2*)(C + (long long)r0 * ldc + col)       = make_float2(v00, v01);
                *(float2*)(C + (long long)(r0 + 8) * ldc + col) = make_float2(v10, v11);
            }
        }
    }
}

// ------------------- rmsnorm (in place), optional tf32 rounding ---------------
__global__ void rmsnorm_kernel(float* __restrict__ data,
                               const float* __restrict__ gamma, int width,
                               int tf32out)
{
    float* p = data + (long long)blockIdx.x * width;
    const int tid = threadIdx.x;
    float ss = 0.f;
    for (int i = tid * 4; i < width; i += 512) {
        float4 v = *(const float4*)(p + i);
        ss += v.x * v.x + v.y * v.y + v.z * v.z + v.w * v.w;
    }
#pragma unroll
    for (int off = 16; off; off >>= 1) ss += __shfl_xor_sync(~0u, ss, off);
    __shared__ float ws[4];
    if ((tid & 31) == 0) ws[tid >> 5] = ss;
    __syncthreads();
    const float inv = rsqrtf((ws[0] + ws[1] + ws[2] + ws[3]) / (float)width + 1e-6f);
    for (int i = tid * 4; i < width; i += 512) {
        float4 v = *(const float4*)(p + i);
        float4 g = *(const float4*)(gamma + i);
        v.x *= inv * g.x; v.y *= inv * g.y; v.z *= inv * g.z; v.w *= inv * g.w;
        if (tf32out) {
            v.x = __uint_as_float(f2tf(v.x)); v.y = __uint_as_float(f2tf(v.y));
            v.z = __uint_as_float(f2tf(v.z)); v.w = __uint_as_float(f2tf(v.w));
        }
        *(float4*)(p + i) = v;
    }
}

// ------------------- RoPE (in place), tf32-rounded output ---------------------
__device__ __forceinline__ void rope_pair(float* p, int i, int m, float scale)
{
    const float x1 = p[i], x2 = p[i + 32];
    const float pos = (float)(m & (S_ - 1));
    const float inv_freq = exp2f(-(float)i * (13.287712379549449f / 32.f));
    float sn, cs;
    sincosf(pos * inv_freq, &sn, &cs);
    p[i]      = __uint_as_float(f2tf((x1 * cs - x2 * sn) * scale));
    p[i + 32] = __uint_as_float(f2tf((x1 * sn + x2 * cs) * scale));
}

__global__ void rope_q_kernel(float* __restrict__ q)
{
    const int idx = blockIdx.x * 256 + threadIdx.x;
    const int i = idx & 31, rest = idx >> 5;
    const int h = rest & (H_ - 1), m = rest >> 4;
    rope_pair(q + (long long)m * (H_ * RD_) + h * RD_, i, m, SM_SCALE);
}

__global__ void rope_k_kernel(float* __restrict__ k)
{
    const int idx = blockIdx.x * 256 + threadIdx.x;
    const int i = idx & 31, m = idx >> 5;
    rope_pair(k + (long long)m * RD_, i, m, 1.f);
}

// ------------------- tf32 tensor-core causal flash attention ------------------
// grid (S/32, H, B), 256 threads (8 warps). BM=32, BN=64.
// Inputs pre-rounded to tf32 (Q side pre-scaled by 1/sqrt(192)).
// Score: warp = m16 x n32 x k288 (2-way k-split); kh=0 writes partials,
//        kh=1 adds in place (ordered by barrier) -> single 32x68 P buffer.
// PV:    warp = m32 x n64 (dedup'd V reads).
#define KSTR 580
#define PSTR 68
__global__ __launch_bounds__(256, 1) void mla_attn_kernel(
    const float* __restrict__ qabs,   // [H][MT][512]  tf32*scale
    const float* __restrict__ qrope,  // [MT][H*64]    tf32*scale
    const float* __restrict__ kv,     // [MT][512]     tf32
    const float* __restrict__ krope,  // [MT][64]      tf32
    float* __restrict__ lat)          // [H][MT][512]
{
    extern __shared__ float smf[];
    unsigned* uQ  = (unsigned*)smf;            // [32][580]
    unsigned* uK  = uQ + 32 * KSTR;            // [64][580]
    float* sP     = (float*)(uK + 64 * KSTR);  // [32][68]
    float* sAlpha = sP + 32 * PSTR;            // [32]
    float* sL     = sAlpha + 32;               // [32]
    unsigned* uP  = (unsigned*)sP;

    const int qt = blockIdx.x, h = blockIdx.y, b = blockIdx.z;
    const int tid = threadIdx.x;
    const int warp = tid >> 5, lane = tid & 31;
    const int gid = lane >> 2, tig = lane & 3;
    const long long mbase = (long long)b * S_;
    const int q0 = qt * 32;

    // ---- load Q tile raw (pre-rounded tf32 bits)
    {
        const unsigned* qa = (const unsigned*)(qabs + ((long long)h * MT + mbase + q0) * KL_);
        for (int idx = tid; idx < 32 * 128; idx += 256) {
            const int r = idx >> 7, c4 = (idx & 127) * 4;
            uint4 v = *(const uint4*)(qa + (long long)r * KL_ + c4);
            *(uint4*)(uQ + r * KSTR + c4) = v;
        }
        const unsigned* qr = (const unsigned*)(qrope + (mbase + q0) * (H_ * RD_) + h * RD_);
        for (int idx = tid; idx < 32 * 16; idx += 256) {
            const int r = idx >> 4, c4 = (idx & 15) * 4;
            uint4 v = *(const uint4*)(qr + (long long)r * (H_ * RD_) + c4);
            *(uint4*)(uQ + r * KSTR + KL_ + c4) = v;
        }
    }

    // score roles: kh = k-half, nh = col-half(32), mh = row-half(16)
    const int kh = warp & 1;
    const int nh = (warp >> 1) & 1;
    const int mh = warp >> 2;
    const int m0w = mh * 16, n0w = nh * 32, k0w = kh * 288;

    // softmax ownership
    const int srow = tid >> 3;
    const int scb  = (tid & 7) * 8;
    float m_run = -INFINITY, l_run = 0.f;

    // PV: warp owns cols pc0..pc0+63, both row groups
    const int pc0 = warp * 64;
    float acc[2][8][4];
#pragma unroll
    for (int mg = 0; mg < 2; mg++)
#pragma unroll
        for (int nt = 0; nt < 8; nt++)
#pragma unroll
            for (int j = 0; j < 4; j++) acc[mg][nt][j] = 0.f;

    const int ntiles = (q0 + 31) / 64 + 1;
    for (int tt = 0; tt < ntiles; tt++) {
        const int t0 = tt * 64;
        __syncthreads();                 // prev PV done with uK/uP
        // ---- load K tile raw (64 x 576 tf32 bits)
        {
            const unsigned* kvp = (const unsigned*)(kv + (mbase + t0) * KL_);
            for (int idx = tid; idx < 64 * 128; idx += 256) {
                const int r = idx >> 7, c4 = (idx & 127) * 4;
                uint4 v = *(const uint4*)(kvp + (long long)r * KL_ + c4);
                *(uint4*)(uK + r * KSTR + c4) = v;
            }
            const unsigned* krp = (const unsigned*)(krope + (mbase + t0) * RD_);
            for (int idx = tid; idx < 64 * 16; idx += 256) {
                const int r = idx >> 4, c4 = (idx & 15) * 4;
                uint4 v = *(const uint4*)(krp + (long long)r * RD_ + c4);
                *(uint4*)(uK + r * KSTR + KL_ + c4) = v;
            }
        }
        __syncthreads();

        // ---- score: m16 x n32 x k288 per warp
        float c[4][4];
#pragma unroll
        for (int nt = 0; nt < 4; nt++)
#pragma unroll
            for (int j = 0; j < 4; j++) c[nt][j] = 0.f;
        {
            const unsigned* qp0 = uQ + (m0w + gid) * KSTR + k0w + tig;
            const unsigned* qp1 = uQ + (m0w + gid + 8) * KSTR + k0w + tig;
            const unsigned* kb0 = uK + (n0w + gid) * KSTR + k0w + tig;
            const unsigned* kb1 = uK + (n0w + 8 + gid) * KSTR + k0w + tig;
            const unsigned* kb2 = uK + (n0w + 16 + gid) * KSTR + k0w + tig;
            const unsigned* kb3 = uK + (n0w + 24 + gid) * KSTR + k0w + tig;
#pragma unroll 4
            for (int kc = 0; kc < 36; kc++) {
                const int k = kc * 8;
                unsigned a0 = qp0[k], a1 = qp1[k], a2 = qp0[k + 4], a3 = qp1[k + 4];
                mma_tf32(c[0], a0, a1, a2, a3, kb0[k], kb0[k + 4]);
                mma_tf32(c[1], a0, a1, a2, a3, kb1[k], kb1[k + 4]);
                mma_tf32(c[2], a0, a1, a2, a3, kb2[k], kb2[k + 4]);
                mma_tf32(c[3], a0, a1, a2, a3, kb3[k], kb3[k + 4]);
            }
        }
        // ---- k-split reduction into single buffer (ordered)
        if (kh == 0) {
#pragma unroll
            for (int nt = 0; nt < 4; nt++) {
                float* p0 = sP + (m0w + gid) * PSTR + n0w + nt * 8 + tig * 2;
                float* p1 = sP + (m0w + gid + 8) * PSTR + n0w + nt * 8 + tig * 2;
                *(float2*)p0 = make_float2(c[nt][0], c[nt][1]);
                *(float2*)p1 = make_float2(c[nt][2], c[nt][3]);
            }
        }
        __syncthreads();
        if (kh == 1) {
#pragma unroll
            for (int nt = 0; nt < 4; nt++) {
                float* p0 = sP + (m0w + gid) * PSTR + n0w + nt * 8 + tig * 2;
                float* p1 = sP + (m0w + gid + 8) * PSTR + n0w + nt * 8 + tig * 2;
                float2 v0 = *(float2*)p0, v1 = *(float2*)p1;
                *(float2*)p0 = make_float2(v0.x + c[nt][0], v0.y + c[nt][1]);
                *(float2*)p1 = make_float2(v1.x + c[nt][2], v1.y + c[nt][3]);
            }
        }
        __syncthreads();

        // ---- online softmax (scale pre-folded into Q)
        {
            const int rglob = q0 + srow;
            float s[8];
            float4 v0 = *(const float4*)&sP[srow * PSTR + scb];
            float4 v1 = *(const float4*)&sP[srow * PSTR + scb + 4];
            s[0] = v0.x; s[1] = v0.y; s[2] = v0.z; s[3] = v0.w;
            s[4] = v1.x; s[5] = v1.y; s[6] = v1.z; s[7] = v1.w;
            float mx = -INFINITY;
#pragma unroll
            for (int j = 0; j < 8; j++) {
                if (t0 + scb + j > rglob) s[j] = -INFINITY;
                mx = fmaxf(mx, s[j]);
            }
#pragma unroll
            for (int off = 1; off < 8; off <<= 1)
                mx = fmaxf(mx, __shfl_xor_sync(~0u, mx, off, 8));
            const float mnew = fmaxf(m_run, mx);
            const float alpha = expf(m_run - mnew);
            float lsum = 0.f;
#pragma unroll
            for (int j = 0; j < 8; j++) { s[j] = expf(s[j] - mnew); lsum += s[j]; }
#pragma unroll
            for (int off = 1; off < 8; off <<= 1)
                lsum += __shfl_xor_sync(~0u, lsum, off, 8);
            l_run = l_run * alpha + lsum;
            m_run = mnew;
            unsigned* d = uP + srow * PSTR + scb;
#pragma unroll
            for (int j = 0; j < 8; j++) d[j] = f2tf(s[j]);
            if ((tid & 7) == 0) sAlpha[srow] = alpha;
        }
        __syncthreads();

        // ---- PV: warp = m32 x n64, acc = acc*alpha + P @ V
        {
            const float a0r = sAlpha[gid];
            const float a1r = sAlpha[gid + 8];
            const float a2r = sAlpha[gid + 16];
            const float a3r = sAlpha[gid + 24];
#pragma unroll
            for (int nt = 0; nt < 8; nt++) {
                acc[0][nt][0] *= a0r; acc[0][nt][1] *= a0r;
                acc[0][nt][2] *= a1r; acc[0][nt][3] *= a1r;
                acc[1][nt][0] *= a2r; acc[1][nt][1] *= a2r;
                acc[1][nt][2] *= a3r; acc[1][nt][3] *= a3r;
            }
#pragma unroll
            for (int kc = 0; kc < 8; kc++) {
                const int kk = kc * 8;
                unsigned pa[2][4];
#pragma unroll
                for (int mg = 0; mg < 2; mg++) {
                    const unsigned* pp = uP + (mg * 16 + gid) * PSTR + kk + tig;
                    pa[mg][0] = pp[0];
                    pa[mg][1] = pp[8 * PSTR];
                    pa[mg][2] = pp[4];
                    pa[mg][3] = pp[8 * PSTR + 4];
                }
                const unsigned* v0 = uK + (kk + tig) * KSTR + pc0 + gid;
                const unsigned* v1 = uK + (kk + tig + 4) * KSTR + pc0 + gid;
#pragma unroll
                for (int nt = 0; nt < 8; nt++) {
                    unsigned b0 = v0[nt * 8], b1 = v1[nt * 8];
                    mma_tf32(acc[0][nt], pa[0][0], pa[0][1], pa[0][2], pa[0][3], b0, b1);
                    mma_tf32(acc[1][nt], pa[1][0], pa[1][1], pa[1][2], pa[1][3], b0, b1);
                }
            }
        }
    }

    // ---- epilogue
    if ((tid & 7) == 0) sL[srow] = l_run;
    __syncthreads();
    float* outp = lat + ((long long)h * MT + mbase + q0) * KL_;
#pragma unroll
    for (int mg = 0; mg < 2; mg++) {
        const float invL = 1.f / sL[mg * 16 + gid];
        const float invH = 1.f / sL[mg * 16 + gid + 8];
        const int rL = mg * 16 + gid, rH = rL + 8;
#pragma unroll
        for (int nt = 0; nt < 8; nt++) {
            const int col = pc0 + nt * 8 + tig * 2;
            *(float2*)(outp + (long long)rL * KL_ + col) =
                make_float2(acc[mg][nt][0] * invL, acc[mg][nt][1] * invL);
            *(float2*)(outp + (long long)rH * KL_ + col) =
                make_float2(acc[mg][nt][2] * invH, acc[mg][nt][3] * invH);
        }
    }
}

// ------------------- launch ---------------------------------------------------
extern "C" void kernel_launch(void* const* d_in, const int* in_sizes, int n_in,
                              void* d_out, int out_size)
{
    const float* x      = (const float*)d_in[0];
    const float* w_qd   = (const float*)d_in[3];
    const float* b_qd   = (const float*)d_in[4];
    const float* gam_q  = (const float*)d_in[5];
    const float* w_qn   = (const float*)d_in[6];
    const float* b_qn   = (const float*)d_in[7];
    const float* w_qr   = (const float*)d_in[8];
    const float* b_qr   = (const float*)d_in[9];
    const float* w_kvd  = (const float*)d_in[10];
    const float* b_kvd  = (const float*)d_in[11];
    const float* gam_kv = (const float*)d_in[12];
    const float* w_ku   = (const float*)d_in[13];
    const float* w_vu   = (const float*)d_in[15];
    const float* w_kr   = (const float*)d_in[17];
    const float* b_kr   = (const float*)d_in[18];
    const float* gates  = (const float*)d_in[19];
    const float* w_o    = (const float*)d_in[20];
    const float* b_o    = (const float*)d_in[21];
    float* out = (float*)d_out;

    float *qc, *qnope, *qrope, *kvp, *krope, *qabs, *lat, *outhd;
    cudaGetSymbolAddress((void**)&qc,    g_qc);
    cudaGetSymbolAddress((void**)&qnope, g_qnope);
    cudaGetSymbolAddress((void**)&qrope, g_qrope);
    cudaGetSymbolAddress((void**)&kvp,   g_kv);
    cudaGetSymbolAddress((void**)&krope, g_krope);
    cudaGetSymbolAddress((void**)&qabs,  g_qabs);
    cudaGetSymbolAddress((void**)&lat,   g_lat);
    cudaGetSymbolAddress((void**)&outhd, g_outhd);

    const int smem_attn = (32 * KSTR + 64 * KSTR + 32 * PSTR + 64) * sizeof(float);
    cudaFuncSetAttribute(mla_attn_kernel,
                         cudaFuncAttributeMaxDynamicSharedMemorySize, smem_attn);

    dim3 blk(256);
    gemm_tf32<true><<<dim3(QL_ / 128, MT / 128, 1), blk>>>(
        x, D_, 0, w_qd, D_, 0, qc, QL_, 0, QL_, D_, b_qd, nullptr, 1.f, 0);
    rmsnorm_kernel<<<MT, 128>>>(qc, gam_q, QL_, 0);
    gemm_tf32<true><<<dim3(D_ / 128, MT / 128, 1), blk>>>(
        qc, QL_, 0, w_qn, QL_, 0, qnope, D_, 0, D_, QL_, b_qn, nullptr, 1.f, 0);
    gemm_tf32<true><<<dim3((H_ * RD_) / 128, MT / 128, 1), blk>>>(
        qc, QL_, 0, w_qr, QL_, 0, qrope, H_ * RD_, 0, H_ * RD_, QL_, b_qr, nullptr,
        1.f, 0);
    rope_q_kernel<<<MT * H_ * 32 / 256, 256>>>(qrope);   // *SM_SCALE, tf32-round
    gemm_tf32<true><<<dim3(KL_ / 128, MT / 128, 1), blk>>>(
        x, D_, 0, w_kvd, D_, 0, kvp, KL_, 0, KL_, D_, b_kvd, nullptr, 1.f, 0);
    rmsnorm_kernel<<<MT, 128>>>(kvp, gam_kv, KL_, 1);    // tf32-round
    gemm_tf32<true><<<dim3(1, MT / 128, 1), blk>>>(
        x, D_, 0, w_kr, D_, 0, krope, RD_, 0, RD_, D_, b_kr, nullptr, 1.f, 0);
    rope_k_kernel<<<MT * 32 / 256, 256>>>(krope);        // tf32-round
    gemm_tf32<false><<<dim3(KL_ / 128, MT / 128, H_), blk>>>(
        qnope, D_, HD_, w_ku, KL_, (long long)HD_ * KL_,
        qabs, KL_, (long long)MT * KL_, KL_, HD_, nullptr, nullptr,
        SM_SCALE, 1);                                    // *SM_SCALE, tf32-round
    mla_attn_kernel<<<dim3(S_ / 32, H_, B_), blk, smem_attn>>>(
        qabs, qrope, kvp, krope, lat);
    gemm_tf32<true><<<dim3(1, MT / 128, H_), blk>>>(
        lat, KL_, (long long)MT * KL_, w_vu, KL_, (long long)HD_ * KL_,
        outhd, D_, HD_, HD_, KL_, nullptr, gates, 1.f, 0);
    gemm_tf32<true><<<dim3(D_ / 128, MT / 128, 1), blk>>>(
        outhd, D_, 0, w_o, D_, 0, out, D_, 0, D_, D_, b_o, nullptr, 1.f, 0);
}

// round 8
// speedup vs baseline: 4.3260x; 1.0208x over previous
#include <cuda_runtime.h>
#include <cuda_bf16.h>
#include <math.h>

#define B_  4
#define S_  2048
#define D_  2048
#define H_  16
#define HD_ 128
#define RD_ 64
#define QL_ 512
#define KL_ 512
#define MT  (B_*S_)
#define DK_ 576
#define SM_SCALE 0.07216878364870323f  // 1/sqrt(192)

// ------------------- scratch (device globals; no runtime allocs) ------------
__device__ float g_qc   [(size_t)MT * QL_];
__device__ float g_qnope[(size_t)MT * D_];
__device__ float g_qrope[(size_t)MT * (H_ * RD_)];
__device__ float g_kv   [(size_t)MT * KL_];
__device__ float g_krope[(size_t)MT * RD_];
__device__ float g_qabs [(size_t)H_ * MT * KL_];
__device__ float g_lat  [(size_t)H_ * MT * KL_];
__device__ float g_outhd[(size_t)MT * D_];

// ------------------- tf32 mma helpers ----------------------------------------
__device__ __forceinline__ unsigned f2tf(float f)
{
    unsigned u; asm("cvt.rna.tf32.f32 %0, %1;" : "=r"(u) : "f"(f)); return u;
}
__device__ __forceinline__ void mma_tf32(float c[4],
    unsigned a0, unsigned a1, unsigned a2, unsigned a3,
    unsigned b0, unsigned b1)
{
    asm volatile("mma.sync.aligned.m16n8k8.row.col.f32.tf32.tf32.f32 "
                 "{%0,%1,%2,%3},{%4,%5,%6,%7},{%8,%9},{%0,%1,%2,%3};"
                 : "+f"(c[0]), "+f"(c[1]), "+f"(c[2]), "+f"(c[3])
                 : "r"(a0), "r"(a1), "r"(a2), "r"(a3), "r"(b0), "r"(b1));
}

// ------------------- tf32 tensor-core GEMM ------------------------------------
// C[M,N] = ((A @ B(^T)) + bias) * sigmoid(gates[z]) * uscale, opt tf32-rounded.
#define GKS 36
template<bool TRANSB>
__global__ __launch_bounds__(256) void gemm_tf32(
    const float* __restrict__ A, int lda, long long sAz,
    const float* __restrict__ B, int ldb, long long sBz,
    float* __restrict__ C, int ldc, long long sCz,
    int N, int K,
    const float* __restrict__ bias,
    const float* __restrict__ gates,
    float uscale, int tf32out)
{
    __shared__ unsigned sA[128 * GKS];
    __shared__ unsigned sB[128 * GKS];

    const int z = blockIdx.z;
    A += (long long)z * sAz;  B += (long long)z * sBz;  C += (long long)z * sCz;

    const int tid = threadIdx.x;
    const int warp = tid >> 5, lane = tid & 31;
    const int gid = lane >> 2, tig = lane & 3;
    const int m0 = blockIdx.y * 128, n0 = blockIdx.x * 128;
    const int wm = (warp & 3) * 32;
    const int wn = (warp >> 2) * 64;

    float acc[2][8][4];
#pragma unroll
    for (int mt = 0; mt < 2; mt++)
#pragma unroll
        for (int nt = 0; nt < 8; nt++)
#pragma unroll
            for (int j = 0; j < 4; j++) acc[mt][nt][j] = 0.f;

    for (int k0 = 0; k0 < K; k0 += 32) {
#pragma unroll
        for (int i = 0; i < 4; i++) {
            const int lin = tid + i * 256;
            const int r = lin >> 3, c4 = (lin & 7) * 4;
            float4 v = *(const float4*)(A + (long long)(m0 + r) * lda + k0 + c4);
            unsigned* d = sA + r * GKS + c4;
            d[0] = f2tf(v.x); d[1] = f2tf(v.y); d[2] = f2tf(v.z); d[3] = f2tf(v.w);
        }
        if (TRANSB) {
#pragma unroll
            for (int i = 0; i < 4; i++) {
                const int lin = tid + i * 256;
                const int r = lin >> 3, c4 = (lin & 7) * 4;
                float4 v = make_float4(0.f, 0.f, 0.f, 0.f);
                if (n0 + r < N)
                    v = *(const float4*)(B + (long long)(n0 + r) * ldb + k0 + c4);
                unsigned* d = sB + r * GKS + c4;
                d[0] = f2tf(v.x); d[1] = f2tf(v.y); d[2] = f2tf(v.z); d[3] = f2tf(v.w);
            }
        } else {
#pragma unroll
            for (int i = 0; i < 16; i++) {
                const int lin = tid + i * 256;
                const int n = lin & 127, k = lin >> 7;
                float v = (n0 + n < N) ? B[(long long)(k0 + k) * ldb + n0 + n] : 0.f;
                sB[n * GKS + k] = f2tf(v);
            }
        }
        __syncthreads();

#pragma unroll
        for (int kk = 0; kk < 4; kk++) {
            const int k8 = kk * 8;
            unsigned a[2][4], b[8][2];
#pragma unroll
            for (int mt = 0; mt < 2; mt++) {
                const unsigned* p = sA + (wm + mt * 16 + gid) * GKS + k8 + tig;
                a[mt][0] = p[0];
                a[mt][1] = p[8 * GKS];
                a[mt][2] = p[4];
                a[mt][3] = p[8 * GKS + 4];
            }
#pragma unroll
            for (int nt = 0; nt < 8; nt++) {
                const unsigned* p = sB + (wn + nt * 8 + gid) * GKS + k8 + tig;
                b[nt][0] = p[0];
                b[nt][1] = p[4];
            }
#pragma unroll
            for (int mt = 0; mt < 2; mt++)
#pragma unroll
                for (int nt = 0; nt < 8; nt++)
                    mma_tf32(acc[mt][nt], a[mt][0], a[mt][1], a[mt][2], a[mt][3],
                             b[nt][0], b[nt][1]);
        }
        __syncthreads();
    }

    float scale = uscale;
    if (gates) scale *= 1.f / (1.f + expf(-gates[z]));
#pragma unroll
    for (int mt = 0; mt < 2; mt++) {
        const int r0 = m0 + wm + mt * 16 + gid;
#pragma unroll
        for (int nt = 0; nt < 8; nt++) {
            const int col = n0 + wn + nt * 8 + tig * 2;
            if (col < N) {
                float bx = 0.f, by = 0.f;
                if (bias) { bx = bias[col]; by = bias[col + 1]; }
                float v00 = (acc[mt][nt][0] + bx) * scale;
                float v01 = (acc[mt][nt][1] + by) * scale;
                float v10 = (acc[mt][nt][2] + bx) * scale;
                float v11 = (acc[mt][nt][3] + by) * scale;
                if (tf32out) {
                    v00 = __uint_as_float(f2tf(v00));
                    v01 = __uint_as_float(f2tf(v01));
                    v10 = __uint_as_float(f2tf(v10));
                    v11 = __uint_as_float(f2tf(v11));
                }
                *(float2*)(C + (long long)r0 * ldc + col)       = make_float2(v00, v01);
                *(float2*)(C + (long long)(r0 + 8) * ldc + col) = make_float2(v10, v11);
            }
        }
    }
}

// ------------------- rmsnorm (in place), optional tf32 rounding ---------------
__global__ void rmsnorm_kernel(float* __restrict__ data,
                               const float* __restrict__ gamma, int width,
                               int tf32out)
{
    float* p = data + (long long)blockIdx.x * width;
    const int tid = threadIdx.x;
    float ss = 0.f;
    for (int i = tid * 4; i < width; i += 512) {
        float4 v = *(const float4*)(p + i);
        ss += v.x * v.x + v.y * v.y + v.z * v.z + v.w * v.w;
    }
#pragma unroll
    for (int off = 16; off; off >>= 1) ss += __shfl_xor_sync(~0u, ss, off);
    __shared__ float ws[4];
    if ((tid & 31) == 0) ws[tid >> 5] = ss;
    __syncthreads();
    const float inv = rsqrtf((ws[0] + ws[1] + ws[2] + ws[3]) / (float)width + 1e-6f);
    for (int i = tid * 4; i < width; i += 512) {
        float4 v = *(const float4*)(p + i);
        float4 g = *(const float4*)(gamma + i);
        v.x *= inv * g.x; v.y *= inv * g.y; v.z *= inv * g.z; v.w *= inv * g.w;
        if (tf32out) {
            v.x = __uint_as_float(f2tf(v.x)); v.y = __uint_as_float(f2tf(v.y));
            v.z = __uint_as_float(f2tf(v.z)); v.w = __uint_as_float(f2tf(v.w));
        }
        *(float4*)(p + i) = v;
    }
}

// ------------------- RoPE (in place), tf32-rounded output ---------------------
__device__ __forceinline__ void rope_pair(float* p, int i, int m, float scale)
{
    const float x1 = p[i], x2 = p[i + 32];
    const float pos = (float)(m & (S_ - 1));
    const float inv_freq = exp2f(-(float)i * (13.287712379549449f / 32.f));
    float sn, cs;
    sincosf(pos * inv_freq, &sn, &cs);
    p[i]      = __uint_as_float(f2tf((x1 * cs - x2 * sn) * scale));
    p[i + 32] = __uint_as_float(f2tf((x1 * sn + x2 * cs) * scale));
}

__global__ void rope_q_kernel(float* __restrict__ q)
{
    const int idx = blockIdx.x * 256 + threadIdx.x;
    const int i = idx & 31, rest = idx >> 5;
    const int h = rest & (H_ - 1), m = rest >> 4;
    rope_pair(q + (long long)m * (H_ * RD_) + h * RD_, i, m, SM_SCALE);
}

__global__ void rope_k_kernel(float* __restrict__ k)
{
    const int idx = blockIdx.x * 256 + threadIdx.x;
    const int i = idx & 31, m = idx >> 5;
    rope_pair(k + (long long)m * RD_, i, m, 1.f);
}

// ------------------- tf32 tensor-core causal flash attention ------------------
// grid (S/32, H, B), 512 threads (16 warps). BM=32, BN=64.
// Inputs pre-rounded to tf32 (Q side pre-scaled by 1/sqrt(192)).
// Score: warp = m16 x n16 x k288 (2 kh x 4 nh x 2 mh); single-buffer ordered
//        k-reduction (kh=0 writes, kh=1 adds).
// Softmax: 16 thr/row x 4 cols, __expf.
// PV:    warp = m16 x n64 (2 mg x 8 col groups).
#define KSTR 580
#define PSTR 68
__global__ __launch_bounds__(512, 1) void mla_attn_kernel(
    const float* __restrict__ qabs,   // [H][MT][512]  tf32*scale
    const float* __restrict__ qrope,  // [MT][H*64]    tf32*scale
    const float* __restrict__ kv,     // [MT][512]     tf32
    const float* __restrict__ krope,  // [MT][64]      tf32
    float* __restrict__ lat)          // [H][MT][512]
{
    extern __shared__ float smf[];
    unsigned* uQ  = (unsigned*)smf;            // [32][580]
    unsigned* uK  = uQ + 32 * KSTR;            // [64][580]
    float* sP     = (float*)(uK + 64 * KSTR);  // [32][68]
    float* sAlpha = sP + 32 * PSTR;            // [32]
    float* sL     = sAlpha + 32;               // [32]
    unsigned* uP  = (unsigned*)sP;

    const int qt = blockIdx.x, h = blockIdx.y, b = blockIdx.z;
    const int tid = threadIdx.x;
    const int warp = tid >> 5, lane = tid & 31;
    const int gid = lane >> 2, tig = lane & 3;
    const long long mbase = (long long)b * S_;
    const int q0 = qt * 32;

    // ---- load Q tile raw (pre-rounded tf32 bits)
    {
        const unsigned* qa = (const unsigned*)(qabs + ((long long)h * MT + mbase + q0) * KL_);
#pragma unroll
        for (int i = 0; i < 8; i++) {
            const int idx = tid + i * 512;
            const int r = idx >> 7, c4 = (idx & 127) * 4;
            uint4 v = *(const uint4*)(qa + (long long)r * KL_ + c4);
            *(uint4*)(uQ + r * KSTR + c4) = v;
        }
        const unsigned* qr = (const unsigned*)(qrope + (mbase + q0) * (H_ * RD_) + h * RD_);
        {
            const int r = tid >> 4, c4 = (tid & 15) * 4;
            uint4 v = *(const uint4*)(qr + (long long)r * (H_ * RD_) + c4);
            *(uint4*)(uQ + r * KSTR + KL_ + c4) = v;
        }
    }

    // score roles: kh = k-half, nh = col-16-group, mh = row-half
    const int kh = warp & 1;
    const int nh = (warp >> 1) & 3;
    const int mh = (warp >> 3) & 1;
    const int m0w = mh * 16, n0w = nh * 16, k0w = kh * 288;

    // softmax ownership: 16 threads per row, 4 cols each
    const int srow = tid >> 4;
    const int scb  = (tid & 15) * 4;
    float m_run = -INFINITY, l_run = 0.f;

    // PV roles: warp = m16 x n64
    const int mg  = warp & 1;
    const int pc0 = (warp >> 1) * 64;
    float acc[8][4];
#pragma unroll
    for (int nt = 0; nt < 8; nt++)
#pragma unroll
        for (int j = 0; j < 4; j++) acc[nt][j] = 0.f;

    const int ntiles = (q0 + 31) / 64 + 1;
    for (int tt = 0; tt < ntiles; tt++) {
        const int t0 = tt * 64;
        __syncthreads();                 // prev PV done with uK/uP
        // ---- load K tile raw (64 x 576 tf32 bits)
        {
            const unsigned* kvp = (const unsigned*)(kv + (mbase + t0) * KL_);
#pragma unroll
            for (int i = 0; i < 16; i++) {
                const int idx = tid + i * 512;
                const int r = idx >> 7, c4 = (idx & 127) * 4;
                uint4 v = *(const uint4*)(kvp + (long long)r * KL_ + c4);
                *(uint4*)(uK + r * KSTR + c4) = v;
            }
            const unsigned* krp = (const unsigned*)(krope + (mbase + t0) * RD_);
#pragma unroll
            for (int i = 0; i < 2; i++) {
                const int idx = tid + i * 512;
                const int r = idx >> 4, c4 = (idx & 15) * 4;
                uint4 v = *(const uint4*)(krp + (long long)r * RD_ + c4);
                *(uint4*)(uK + r * KSTR + KL_ + c4) = v;
            }
        }
        __syncthreads();

        // ---- score: m16 x n16 x k288 per warp
        float c0[4] = {0.f, 0.f, 0.f, 0.f}, c1[4] = {0.f, 0.f, 0.f, 0.f};
        {
            const unsigned* qp0 = uQ + (m0w + gid) * KSTR + k0w + tig;
            const unsigned* qp1 = uQ + (m0w + gid + 8) * KSTR + k0w + tig;
            const unsigned* kb0 = uK + (n0w + gid) * KSTR + k0w + tig;
            const unsigned* kb1 = uK + (n0w + 8 + gid) * KSTR + k0w + tig;
#pragma unroll 4
            for (int kc = 0; kc < 36; kc++) {
                const int k = kc * 8;
                unsigned a0 = qp0[k], a1 = qp1[k], a2 = qp0[k + 4], a3 = qp1[k + 4];
                mma_tf32(c0, a0, a1, a2, a3, kb0[k], kb0[k + 4]);
                mma_tf32(c1, a0, a1, a2, a3, kb1[k], kb1[k + 4]);
            }
        }
        // ---- k-split reduction into single buffer (ordered)
        if (kh == 0) {
            float* p0 = sP + (m0w + gid) * PSTR + n0w + tig * 2;
            float* p1 = sP + (m0w + gid + 8) * PSTR + n0w + tig * 2;
            *(float2*)p0       = make_float2(c0[0], c0[1]);
            *(float2*)p1       = make_float2(c0[2], c0[3]);
            *(float2*)(p0 + 8) = make_float2(c1[0], c1[1]);
            *(float2*)(p1 + 8) = make_float2(c1[2], c1[3]);
        }
        __syncthreads();
        if (kh == 1) {
            float* p0 = sP + (m0w + gid) * PSTR + n0w + tig * 2;
            float* p1 = sP + (m0w + gid + 8) * PSTR + n0w + tig * 2;
            float2 v0 = *(float2*)p0, v1 = *(float2*)p1;
            float2 v2 = *(float2*)(p0 + 8), v3 = *(float2*)(p1 + 8);
            *(float2*)p0       = make_float2(v0.x + c0[0], v0.y + c0[1]);
            *(float2*)p1       = make_float2(v1.x + c0[2], v1.y + c0[3]);
            *(float2*)(p0 + 8) = make_float2(v2.x + c1[0], v2.y + c1[1]);
            *(float2*)(p1 + 8) = make_float2(v3.x + c1[2], v3.y + c1[3]);
        }
        __syncthreads();

        // ---- online softmax (scale pre-folded into Q)
        {
            const int rglob = q0 + srow;
            float s[4];
            float4 v0 = *(const float4*)&sP[srow * PSTR + scb];
            s[0] = v0.x; s[1] = v0.y; s[2] = v0.z; s[3] = v0.w;
            float mx = -INFINITY;
#pragma unroll
            for (int j = 0; j < 4; j++) {
                if (t0 + scb + j > rglob) s[j] = -INFINITY;
                mx = fmaxf(mx, s[j]);
            }
#pragma unroll
            for (int off = 1; off < 16; off <<= 1)
                mx = fmaxf(mx, __shfl_xor_sync(~0u, mx, off, 16));
            const float mnew = fmaxf(m_run, mx);
            const float alpha = __expf(m_run - mnew);
            float lsum = 0.f;
#pragma unroll
            for (int j = 0; j < 4; j++) { s[j] = __expf(s[j] - mnew); lsum += s[j]; }
#pragma unroll
            for (int off = 1; off < 16; off <<= 1)
                lsum += __shfl_xor_sync(~0u, lsum, off, 16);
            l_run = l_run * alpha + lsum;
            m_run = mnew;
            unsigned* d = uP + srow * PSTR + scb;
#pragma unroll
            for (int j = 0; j < 4; j++) d[j] = f2tf(s[j]);
            if ((tid & 15) == 0) sAlpha[srow] = alpha;
        }
        __syncthreads();

        // ---- PV: warp = m16 x n64, acc = acc*alpha + P @ V
        {
            const float a0r = sAlpha[mg * 16 + gid];
            const float a1r = sAlpha[mg * 16 + gid + 8];
#pragma unroll
            for (int nt = 0; nt < 8; nt++) {
                acc[nt][0] *= a0r; acc[nt][1] *= a0r;
                acc[nt][2] *= a1r; acc[nt][3] *= a1r;
            }
#pragma unroll
            for (int kc = 0; kc < 8; kc++) {
                const int kk = kc * 8;
                const unsigned* pp = uP + (mg * 16 + gid) * PSTR + kk + tig;
                unsigned pa0 = pp[0];
                unsigned pa1 = pp[8 * PSTR];
                unsigned pa2 = pp[4];
                unsigned pa3 = pp[8 * PSTR + 4];
                const unsigned* v0 = uK + (kk + tig) * KSTR + pc0 + gid;
                const unsigned* v1 = uK + (kk + tig + 4) * KSTR + pc0 + gid;
#pragma unroll
                for (int nt = 0; nt < 8; nt++)
                    mma_tf32(acc[nt], pa0, pa1, pa2, pa3, v0[nt * 8], v1[nt * 8]);
            }
        }
    }

    // ---- epilogue
    if ((tid & 15) == 0) sL[srow] = l_run;
    __syncthreads();
    const float invL = 1.f / sL[mg * 16 + gid];
    const float invH = 1.f / sL[mg * 16 + gid + 8];
    const int rL = mg * 16 + gid, rH = rL + 8;
    float* outp = lat + ((long long)h * MT + mbase + q0) * KL_;
#pragma unroll
    for (int nt = 0; nt < 8; nt++) {
        const int col = pc0 + nt * 8 + tig * 2;
        *(float2*)(outp + (long long)rL * KL_ + col) =
            make_float2(acc[nt][0] * invL, acc[nt][1] * invL);
        *(float2*)(outp + (long long)rH * KL_ + col) =
            make_float2(acc[nt][2] * invH, acc[nt][3] * invH);
    }
}

// ------------------- launch ---------------------------------------------------
extern "C" void kernel_launch(void* const* d_in, const int* in_sizes, int n_in,
                              void* d_out, int out_size)
{
    const float* x      = (const float*)d_in[0];
    const float* w_qd   = (const float*)d_in[3];
    const float* b_qd   = (const float*)d_in[4];
    const float* gam_q  = (const float*)d_in[5];
    const float* w_qn   = (const float*)d_in[6];
    const float* b_qn   = (const float*)d_in[7];
    const float* w_qr   = (const float*)d_in[8];
    const float* b_qr   = (const float*)d_in[9];
    const float* w_kvd  = (const float*)d_in[10];
    const float* b_kvd  = (const float*)d_in[11];
    const float* gam_kv = (const float*)d_in[12];
    const float* w_ku   = (const float*)d_in[13];
    const float* w_vu   = (const float*)d_in[15];
    const float* w_kr   = (const float*)d_in[17];
    const float* b_kr   = (const float*)d_in[18];
    const float* gates  = (const float*)d_in[19];
    const float* w_o    = (const float*)d_in[20];
    const float* b_o    = (const float*)d_in[21];
    float* out = (float*)d_out;

    float *qc, *qnope, *qrope, *kvp, *krope, *qabs, *lat, *outhd;
    cudaGetSymbolAddress((void**)&qc,    g_qc);
    cudaGetSymbolAddress((void**)&qnope, g_qnope);
    cudaGetSymbolAddress((void**)&qrope, g_qrope);
    cudaGetSymbolAddress((void**)&kvp,   g_kv);
    cudaGetSymbolAddress((void**)&krope, g_krope);
    cudaGetSymbolAddress((void**)&qabs,  g_qabs);
    cudaGetSymbolAddress((void**)&lat,   g_lat);
    cudaGetSymbolAddress((void**)&outhd, g_outhd);

    const int smem_attn = (32 * KSTR + 64 * KSTR + 32 * PSTR + 64) * sizeof(float);
    cudaFuncSetAttribute(mla_attn_kernel,
                         cudaFuncAttributeMaxDynamicSharedMemorySize, smem_attn);

    dim3 blk(256);
    gemm_tf32<true><<<dim3(QL_ / 128, MT / 128, 1), blk>>>(
        x, D_, 0, w_qd, D_, 0, qc, QL_, 0, QL_, D_, b_qd, nullptr, 1.f, 0);
    rmsnorm_kernel<<<MT, 128>>>(qc, gam_q, QL_, 0);
    gemm_tf32<true><<<dim3(D_ / 128, MT / 128, 1), blk>>>(
        qc, QL_, 0, w_qn, QL_, 0, qnope, D_, 0, D_, QL_, b_qn, nullptr, 1.f, 0);
    gemm_tf32<true><<<dim3((H_ * RD_) / 128, MT / 128, 1), blk>>>(
        qc, QL_, 0, w_qr, QL_, 0, qrope, H_ * RD_, 0, H_ * RD_, QL_, b_qr, nullptr,
        1.f, 0);
    rope_q_kernel<<<MT * H_ * 32 / 256, 256>>>(qrope);   // *SM_SCALE, tf32-round
    gemm_tf32<true><<<dim3(KL_ / 128, MT / 128, 1), blk>>>(
        x, D_, 0, w_kvd, D_, 0, kvp, KL_, 0, KL_, D_, b_kvd, nullptr, 1.f, 0);
    rmsnorm_kernel<<<MT, 128>>>(kvp, gam_kv, KL_, 1);    // tf32-round
    gemm_tf32<true><<<dim3(1, MT / 128, 1), blk>>>(
        x, D_, 0, w_kr, D_, 0, krope, RD_, 0, RD_, D_, b_kr, nullptr, 1.f, 0);
    rope_k_kernel<<<MT * 32 / 256, 256>>>(krope);        // tf32-round
    gemm_tf32<false><<<dim3(KL_ / 128, MT / 128, H_), blk>>>(
        qnope, D_, HD_, w_ku, KL_, (long long)HD_ * KL_,
        qabs, KL_, (long long)MT * KL_, KL_, HD_, nullptr, nullptr,
        SM_SCALE, 1);                                    // *SM_SCALE, tf32-round
    mla_attn_kernel<<<dim3(S_ / 32, H_, B_), dim3(512), smem_attn>>>(
        qabs, qrope, kvp, krope, lat);
    gemm_tf32<true><<<dim3(1, MT / 128, H_), blk>>>(
        lat, KL_, (long long)MT * KL_, w_vu, KL_, (long long)HD_ * KL_,
        outhd, D_, HD_, HD_, KL_, nullptr, gates, 1.f, 0);
    gemm_tf32<true><<<dim3(D_ / 128, MT / 128, 1), blk>>>(
        outhd, D_, 0, w_o, D_, 0, out, D_, 0, D_, D_, b_o, nullptr, 1.f, 0);
}